// round 2
// baseline (speedup 1.0000x reference)
#include <cuda_runtime.h>
#include <math.h>

// Problem constants (fixed shapes)
#define SEQ    2048
#define BATCH  2
#define EMB    1024
#define NH     16
#define HD     64
#define NHEADS (BATCH * NH)     // 32 flattened heads
#define MROWS  (SEQ * BATCH)    // 4096 token rows

// ---------------- scratch (static device memory; no allocs) ----------------
__device__ float g_q[MROWS * EMB];          // Q projection, [S*B, E] plain
__device__ float g_k[MROWS * EMB];
__device__ float g_v[MROWS * EMB];
__device__ float g_qh[NHEADS * SEQ * HD];   // head layout [g, s, d], RoPE'd
__device__ float g_kh[NHEADS * SEQ * HD];
__device__ float g_vh[NHEADS * SEQ * HD];
__device__ float g_attn[MROWS * EMB];       // attention out, [S*B, E] plain

// ---------------- SGEMM: C[M,N] = A[M,K] @ W[N,K]^T, +bias, *scale --------
// Fixed M=MROWS (or per-launch via grid.y), N=EMB, K=EMB.
// 128x128 block tile, BK=8, 256 threads, 8x8 per thread.
#define BM 128
#define BN 128
#define GBK 8
#define TM 8
#define TN 8

__device__ __forceinline__ void gemm_body(const float* __restrict__ A,
                                          const float* __restrict__ W,
                                          const float* __restrict__ bias,
                                          float* __restrict__ C,
                                          float scale)
{
    __shared__ float As[GBK][BM];
    __shared__ float Bs[GBK][BN];

    const int tid = threadIdx.x;
    const int lr  = tid >> 1;          // 0..127 : row within tile (A: m, W: n)
    const int lc  = (tid & 1) << 2;    // 0 or 4 : k offset within BK
    const int m0  = blockIdx.y * BM;
    const int n0  = blockIdx.x * BN;

    const float* Ab = A + (size_t)m0 * EMB;
    const float* Wb = W + (size_t)n0 * EMB;

    const int tr = (tid >> 4) * TM;    // 0..120
    const int tc = (tid & 15) * TN;    // 0..120

    float acc[TM][TN];
    #pragma unroll
    for (int i = 0; i < TM; i++)
        #pragma unroll
        for (int j = 0; j < TN; j++) acc[i][j] = 0.f;

    for (int k0 = 0; k0 < EMB; k0 += GBK) {
        float4 a4 = *(const float4*)(Ab + (size_t)lr * EMB + k0 + lc);
        float4 b4 = *(const float4*)(Wb + (size_t)lr * EMB + k0 + lc);
        As[lc + 0][lr] = a4.x; As[lc + 1][lr] = a4.y;
        As[lc + 2][lr] = a4.z; As[lc + 3][lr] = a4.w;
        Bs[lc + 0][lr] = b4.x; Bs[lc + 1][lr] = b4.y;
        Bs[lc + 2][lr] = b4.z; Bs[lc + 3][lr] = b4.w;
        __syncthreads();

        #pragma unroll
        for (int kk = 0; kk < GBK; kk++) {
            float4 a0 = *(const float4*)&As[kk][tr];
            float4 a1 = *(const float4*)&As[kk][tr + 4];
            float4 b0 = *(const float4*)&Bs[kk][tc];
            float4 b1 = *(const float4*)&Bs[kk][tc + 4];
            float ra[TM] = {a0.x, a0.y, a0.z, a0.w, a1.x, a1.y, a1.z, a1.w};
            float rb[TN] = {b0.x, b0.y, b0.z, b0.w, b1.x, b1.y, b1.z, b1.w};
            #pragma unroll
            for (int i = 0; i < TM; i++)
                #pragma unroll
                for (int j = 0; j < TN; j++)
                    acc[i][j] = fmaf(ra[i], rb[j], acc[i][j]);
        }
        __syncthreads();
    }

    #pragma unroll
    for (int i = 0; i < TM; i++) {
        float* Cr = C + (size_t)(m0 + tr + i) * EMB + n0 + tc;
        #pragma unroll
        for (int j = 0; j < TN; j += 4) {
            float4 w;
            w.x = (acc[i][j]     + bias[n0 + tc + j])     * scale;
            w.y = (acc[i][j + 1] + bias[n0 + tc + j + 1]) * scale;
            w.z = (acc[i][j + 2] + bias[n0 + tc + j + 2]) * scale;
            w.w = (acc[i][j + 3] + bias[n0 + tc + j + 3]) * scale;
            *(float4*)(Cr + j) = w;
        }
    }
}

// Fused Q/K/V projection: grid.z selects which projection.
__global__ __launch_bounds__(256) void qkv_gemm(
    const float* __restrict__ X,
    const float* __restrict__ Wq, const float* __restrict__ bq,
    const float* __restrict__ Wk, const float* __restrict__ bk,
    const float* __restrict__ Wv, const float* __restrict__ bv)
{
    const int z = blockIdx.z;
    const float* W = (z == 0) ? Wq : (z == 1) ? Wk : Wv;
    const float* b = (z == 0) ? bq : (z == 1) ? bk : bv;
    float* C       = (z == 0) ? g_q : (z == 1) ? g_k : g_v;
    const float scale = (z == 0) ? 0.125f : 1.0f;   // hd^-0.5 = 64^-0.5
    gemm_body(X, W, b, C, scale);
}

__global__ __launch_bounds__(256) void out_gemm(
    const float* __restrict__ Wo, const float* __restrict__ bo,
    float* __restrict__ out)
{
    gemm_body(g_attn, Wo, bo, out, 1.0f);
}

// ---------------- RoPE + transpose to head layout --------------------------
// which=0: q (rope), 1: k (rope), 2: v (copy). dst layout: [(b*NH+h), s, d].
__global__ __launch_bounds__(256) void rope_kernel()
{
    const int which = blockIdx.z;
    const float* src = (which == 0) ? g_q  : (which == 1) ? g_k  : g_v;
    float*       dst = (which == 0) ? g_qh : (which == 1) ? g_kh : g_vh;

    const int idx = blockIdx.x * 256 + threadIdx.x;   // exact: 32*2048*64 elems
    const int d = idx & (HD - 1);
    const int s = (idx >> 6) & (SEQ - 1);
    const int g = idx >> 17;                          // 6 + 11 bits
    const int b  = g >> 4;
    const int hh = g & 15;

    const size_t so = ((size_t)s * BATCH + b) * EMB + hh * HD;
    const float x = src[so + d];
    float outv;
    if (which == 2) {
        outv = x;
    } else {
        const int i = d & 31;
        const float inv_f = powf(10000.f, -(float)(2 * i) * (1.f / 64.f));
        const float ang = (float)s * inv_f;
        float sn, c;
        sincosf(ang, &sn, &c);
        const float partner = src[so + ((d < 32) ? d + 32 : d - 32)];
        outv = fmaf(x, c, ((d < 32) ? -partner : partner) * sn);
    }
    dst[idx] = outv;
}

// ---------------- Flash attention (non-causal, full softmax) ----------------
// 1 thread = 1 query row. q[64] and acc[64] in registers; K/V tiles in smem
// (all lanes read the same address in lockstep -> broadcast, conflict-free).
// Scores staged in smem Ss[j][tid] (stride 128 -> conflict-free) so the
// j-loop stays rolled (small I-footprint, no local-memory spill of s-buffer).
#define BQ  128
#define BKV 32

__global__ __launch_bounds__(BQ) void attn_kernel()
{
    __shared__ float Ks[BKV][HD];
    __shared__ float Vs[BKV][HD];
    __shared__ float Ss[BKV][BQ];

    const int g   = blockIdx.y;                 // head 0..31
    const int tid = threadIdx.x;
    const int s   = blockIdx.x * BQ + tid;      // query row

    const float* qptr = g_qh + ((size_t)g * SEQ + s) * HD;
    float q[HD], acc[HD];
    #pragma unroll
    for (int d = 0; d < HD; d += 4) {
        float4 t = *(const float4*)(qptr + d);
        q[d] = t.x; q[d + 1] = t.y; q[d + 2] = t.z; q[d + 3] = t.w;
        acc[d] = 0.f; acc[d + 1] = 0.f; acc[d + 2] = 0.f; acc[d + 3] = 0.f;
    }
    float m = -1e30f, l = 0.f;

    const float* kb = g_kh + (size_t)g * SEQ * HD;
    const float* vb = g_vh + (size_t)g * SEQ * HD;

    for (int t0 = 0; t0 < SEQ; t0 += BKV) {
        __syncthreads();   // protect tiles from previous iteration's readers
        // cooperative tile load: BKV*HD = 2048 floats each -> 4 float4/thread
        #pragma unroll
        for (int r = 0; r < (BKV * HD) / (BQ * 4); r++) {
            const int idx = (r * BQ + tid) * 4;
            *(float4*)((float*)Ks + idx) = *(const float4*)(kb + (size_t)t0 * HD + idx);
            *(float4*)((float*)Vs + idx) = *(const float4*)(vb + (size_t)t0 * HD + idx);
        }
        __syncthreads();

        // scores for this tile + running tile max
        float tmax = -1e30f;
        for (int j = 0; j < BKV; j++) {
            float sum = 0.f;
            #pragma unroll
            for (int d = 0; d < HD; d += 4) {
                float4 kv = *(const float4*)&Ks[j][d];
                sum += q[d] * kv.x + q[d + 1] * kv.y + q[d + 2] * kv.z + q[d + 3] * kv.w;
            }
            Ss[j][tid] = sum;
            tmax = fmaxf(tmax, sum);
        }

        const float mnew = fmaxf(m, tmax);
        const float corr = __expf(m - mnew);
        l *= corr;
        #pragma unroll
        for (int d = 0; d < HD; d++) acc[d] *= corr;

        for (int j = 0; j < BKV; j++) {
            const float p = __expf(Ss[j][tid] - mnew);
            l += p;
            #pragma unroll
            for (int d = 0; d < HD; d += 4) {
                float4 vv = *(const float4*)&Vs[j][d];
                acc[d]     = fmaf(p, vv.x, acc[d]);
                acc[d + 1] = fmaf(p, vv.y, acc[d + 1]);
                acc[d + 2] = fmaf(p, vv.z, acc[d + 2]);
                acc[d + 3] = fmaf(p, vv.w, acc[d + 3]);
            }
        }
        m = mnew;
    }

    // write to plain [S, B, E] layout for the output projection
    const int b  = g / NH;
    const int hh = g % NH;
    float* o = g_attn + ((size_t)s * BATCH + b) * EMB + hh * HD;
    const float invl = 1.f / l;
    #pragma unroll
    for (int d = 0; d < HD; d += 4) {
        float4 w;
        w.x = acc[d] * invl;     w.y = acc[d + 1] * invl;
        w.z = acc[d + 2] * invl; w.w = acc[d + 3] * invl;
        *(float4*)(o + d) = w;
    }
}

// ---------------- launch ----------------------------------------------------
extern "C" void kernel_launch(void* const* d_in, const int* in_sizes, int n_in,
                              void* d_out, int out_size)
{
    (void)in_sizes; (void)n_in; (void)out_size;
    const float* query = (const float*)d_in[0];
    const float* Wq    = (const float*)d_in[1];
    const float* bq    = (const float*)d_in[2];
    const float* Wk    = (const float*)d_in[3];
    const float* bk    = (const float*)d_in[4];
    const float* Wv    = (const float*)d_in[5];
    const float* bv    = (const float*)d_in[6];
    const float* Wo    = (const float*)d_in[7];
    const float* bo    = (const float*)d_in[8];
    float* out = (float*)d_out;

    // 1) fused QKV projection: 3 x [4096,1024] = [4096,1024]x[1024,1024]^T
    dim3 gq(EMB / BN, MROWS / BM, 3);         // (8, 32, 3)
    qkv_gemm<<<gq, 256>>>(query, Wq, bq, Wk, bk, Wv, bv);

    // 2) RoPE + transpose to head layout (q, k roped; v copied)
    dim3 gr((NHEADS * SEQ * HD) / 256, 1, 3); // (16384, 1, 3)
    rope_kernel<<<gr, 256>>>();

    // 3) flash attention: 32 heads x 16 query blocks of 128 rows
    dim3 ga(SEQ / BQ, NHEADS);                // (16, 32)
    attn_kernel<<<ga, BQ>>>();

    // 4) output projection
    dim3 go(EMB / BN, MROWS / BM);            // (8, 32)
    out_gemm<<<go, 256>>>(Wo, bo, out);
}

// round 4
// speedup vs baseline: 1.1923x; 1.1923x over previous
#include <cuda_runtime.h>
#include <cuda_bf16.h>
#include <cstdint>
#include <math.h>

// Problem constants (fixed shapes)
#define SEQ    2048
#define BATCH  2
#define EMB    1024
#define NH     16
#define HD     64
#define NHEADS (BATCH * NH)     // 32 flattened heads
#define MROWS  (SEQ * BATCH)    // 4096 token rows

// ---------------- scratch (static device memory; no allocs) ----------------
__device__ float g_q[MROWS * EMB];
__device__ float g_k[MROWS * EMB];
__device__ float g_v[MROWS * EMB];
__device__ float g_qh[NHEADS * SEQ * HD];
__device__ float g_kh[NHEADS * SEQ * HD];
__device__ float g_vh[NHEADS * SEQ * HD];
__device__ float g_attn[MROWS * EMB];

// bf16 hi/lo split operands
__device__ __nv_bfloat16 g_xh[MROWS * EMB];
__device__ __nv_bfloat16 g_xl[MROWS * EMB];
__device__ __nv_bfloat16 g_wh[4 * EMB * EMB];   // Wq, Wk, Wv, Wo
__device__ __nv_bfloat16 g_wl[4 * EMB * EMB];
__device__ __nv_bfloat16 g_ah[MROWS * EMB];
__device__ __nv_bfloat16 g_al[MROWS * EMB];

// ======================= helpers ===========================================
__device__ __forceinline__ uint32_t smem_to_u32(const void* smem_ptr) {
    uint32_t addr;
    asm("{ .reg .u64 tmp; cvta.to.shared.u64 tmp, %1; cvt.u32.u64 %0, tmp; }"
        : "=r"(addr) : "l"(smem_ptr));
    return addr;
}

__device__ __forceinline__ void ldm_x4(uint32_t* r, uint32_t addr) {
    asm volatile("ldmatrix.sync.aligned.m8n8.x4.shared.b16 {%0,%1,%2,%3}, [%4];"
                 : "=r"(r[0]), "=r"(r[1]), "=r"(r[2]), "=r"(r[3]) : "r"(addr));
}
__device__ __forceinline__ void ldm_x2(uint32_t* r, uint32_t addr) {
    asm volatile("ldmatrix.sync.aligned.m8n8.x2.shared.b16 {%0,%1}, [%2];"
                 : "=r"(r[0]), "=r"(r[1]) : "r"(addr));
}
__device__ __forceinline__ void mma_bf16(float* d, const uint32_t* a, const uint32_t* b) {
    asm volatile(
        "mma.sync.aligned.m16n8k16.row.col.f32.bf16.bf16.f32 "
        "{%0,%1,%2,%3}, {%4,%5,%6,%7}, {%8,%9}, {%0,%1,%2,%3};"
        : "+f"(d[0]), "+f"(d[1]), "+f"(d[2]), "+f"(d[3])
        : "r"(a[0]), "r"(a[1]), "r"(a[2]), "r"(a[3]), "r"(b[0]), "r"(b[1]));
}

// ======================= fp32 -> bf16 hi/lo conversion ======================
__device__ __forceinline__ void split4(const float4 x, __nv_bfloat162* hi2,
                                       __nv_bfloat162* lo2, size_t i2) {
    __nv_bfloat16 h0 = __float2bfloat16(x.x);
    __nv_bfloat16 h1 = __float2bfloat16(x.y);
    __nv_bfloat16 h2 = __float2bfloat16(x.z);
    __nv_bfloat16 h3 = __float2bfloat16(x.w);
    hi2[i2]     = __nv_bfloat162(h0, h1);
    hi2[i2 + 1] = __nv_bfloat162(h2, h3);
    lo2[i2]     = __nv_bfloat162(__float2bfloat16(x.x - __bfloat162float(h0)),
                                 __float2bfloat16(x.y - __bfloat162float(h1)));
    lo2[i2 + 1] = __nv_bfloat162(__float2bfloat16(x.z - __bfloat162float(h2)),
                                 __float2bfloat16(x.w - __bfloat162float(h3)));
}

__global__ __launch_bounds__(256) void cvt_split(const float* __restrict__ src,
                                                 __nv_bfloat16* __restrict__ hi,
                                                 __nv_bfloat16* __restrict__ lo) {
    const size_t i4 = (size_t)blockIdx.x * 256 + threadIdx.x;
    float4 x = ((const float4*)src)[i4];
    split4(x, (__nv_bfloat162*)hi, (__nv_bfloat162*)lo, i4 * 2);
}

__global__ __launch_bounds__(256) void cvt_w(const float* __restrict__ Wq,
                                             const float* __restrict__ Wk,
                                             const float* __restrict__ Wv,
                                             const float* __restrict__ Wo) {
    const int z = blockIdx.z;
    const float* src = (z == 0) ? Wq : (z == 1) ? Wk : (z == 2) ? Wv : Wo;
    const size_t base4 = (size_t)z * (EMB * EMB / 4);
    const size_t i4 = base4 + (size_t)blockIdx.x * 256 + threadIdx.x;
    float4 x = ((const float4*)src)[(size_t)blockIdx.x * 256 + threadIdx.x];
    split4(x, (__nv_bfloat162*)g_wh, (__nv_bfloat162*)g_wl, i4 * 2);
}

// ======================= mma.sync split-bf16 GEMM ===========================
// C[M,N] = A[M,K] @ W[N,K]^T (+bias)*scale
//   = Ah*Wh + Ah*Wl + Al*Wh   (bf16 mma, fp32 register accumulate)
// CTA 128x128, BK=16, 8 warps (4x2), warp tile 32x64.
#define MM_BK       16
#define TILE_STRIDE 48                  // padded bytes per 16-elem bf16 row
#define TILE_SZ     (128 * TILE_STRIDE) // 6144 bytes per tile
#define STG_SZ      (4 * TILE_SZ)       // Ah, Al, Wh, Wl
#define N_ITERS     (EMB / MM_BK)       // 64

__device__ __forceinline__ void mm_gemm_body(const __nv_bfloat16* __restrict__ Ah,
                                             const __nv_bfloat16* __restrict__ Al,
                                             const __nv_bfloat16* __restrict__ Wh,
                                             const __nv_bfloat16* __restrict__ Wl,
                                             const float* __restrict__ bias,
                                             float* __restrict__ C, float scale,
                                             int m0, int n0)
{
    __shared__ __align__(16) char sm[2 * STG_SZ];   // 49152 B
    const uint32_t smb = smem_to_u32(sm);

    const int tid  = threadIdx.x;
    const int lane = tid & 31;
    const int wid  = tid >> 5;
    const int wm   = wid >> 1;          // 0..3 : warp m position (32 rows)
    const int wn   = wid & 1;           // 0..1 : warp n position (64 cols)

    // global load mapping: thread -> (row 0..127, 16B half 0..1)
    const int lrow  = tid >> 1;
    const int lhalf = tid & 1;
    const uint32_t st_off = (uint32_t)(lrow * TILE_STRIDE + lhalf * 16);

    const __nv_bfloat16* pAh = Ah + (size_t)(m0 + lrow) * EMB + lhalf * 8;
    const __nv_bfloat16* pAl = Al + (size_t)(m0 + lrow) * EMB + lhalf * 8;
    const __nv_bfloat16* pWh = Wh + (size_t)(n0 + lrow) * EMB + lhalf * 8;
    const __nv_bfloat16* pWl = Wl + (size_t)(n0 + lrow) * EMB + lhalf * 8;

    float acc[2][8][4];
    #pragma unroll
    for (int mi = 0; mi < 2; mi++)
        #pragma unroll
        for (int ni = 0; ni < 8; ni++)
            #pragma unroll
            for (int j = 0; j < 4; j++) acc[mi][ni][j] = 0.f;

    // prefetch k=0 into regs
    uint4 vAh = *(const uint4*)pAh;
    uint4 vAl = *(const uint4*)pAl;
    uint4 vWh = *(const uint4*)pWh;
    uint4 vWl = *(const uint4*)pWl;

    for (int k = 0; k < N_ITERS; k++) {
        const int cur = k & 1;
        char* sb = sm + cur * STG_SZ;
        *(uint4*)(sb + 0 * TILE_SZ + st_off) = vAh;
        *(uint4*)(sb + 1 * TILE_SZ + st_off) = vAl;
        *(uint4*)(sb + 2 * TILE_SZ + st_off) = vWh;
        *(uint4*)(sb + 3 * TILE_SZ + st_off) = vWl;
        __syncthreads();

        if (k + 1 < N_ITERS) {          // prefetch next slice (overlaps mma)
            const int ko = (k + 1) * MM_BK;
            vAh = *(const uint4*)(pAh + ko);
            vAl = *(const uint4*)(pAl + ko);
            vWh = *(const uint4*)(pWh + ko);
            vWl = *(const uint4*)(pWl + ko);
        }

        const uint32_t tb = smb + cur * STG_SZ;
        uint32_t aH[2][4], aL[2][4], bH[8][2], bL[8][2];
        #pragma unroll
        for (int mi = 0; mi < 2; mi++) {
            const uint32_t row = wm * 32 + mi * 16 + (lane & 15);
            const uint32_t addr = tb + row * TILE_STRIDE + (lane >> 4) * 16;
            ldm_x4(aH[mi], addr);
            ldm_x4(aL[mi], addr + TILE_SZ);
        }
        #pragma unroll
        for (int ni = 0; ni < 8; ni++) {
            const uint32_t row = wn * 64 + ni * 8 + (lane & 7);
            const uint32_t addr = tb + 2 * TILE_SZ + row * TILE_STRIDE + ((lane >> 3) & 1) * 16;
            ldm_x2(bH[ni], addr);
            ldm_x2(bL[ni], addr + TILE_SZ);
        }

        #pragma unroll
        for (int mi = 0; mi < 2; mi++)
            #pragma unroll
            for (int ni = 0; ni < 8; ni++) {
                mma_bf16(acc[mi][ni], aH[mi], bH[ni]);
                mma_bf16(acc[mi][ni], aH[mi], bL[ni]);
                mma_bf16(acc[mi][ni], aL[mi], bH[ni]);
            }
        __syncthreads();
    }

    // epilogue: frag layout of m16n8 -> rows (lane>>2, +8), cols (lane&3)*2
    #pragma unroll
    for (int mi = 0; mi < 2; mi++) {
        #pragma unroll
        for (int ni = 0; ni < 8; ni++) {
            const int r  = m0 + wm * 32 + mi * 16 + (lane >> 2);
            const int c  = n0 + wn * 64 + ni * 8 + (lane & 3) * 2;
            float2 v0, v1;
            v0.x = (acc[mi][ni][0] + bias[c])     * scale;
            v0.y = (acc[mi][ni][1] + bias[c + 1]) * scale;
            v1.x = (acc[mi][ni][2] + bias[c])     * scale;
            v1.y = (acc[mi][ni][3] + bias[c + 1]) * scale;
            *(float2*)(C + (size_t)r * EMB + c)       = v0;
            *(float2*)(C + (size_t)(r + 8) * EMB + c) = v1;
        }
    }
}

__global__ __launch_bounds__(256, 1) void mm_qkv(const float* __restrict__ bq,
                                                 const float* __restrict__ bk,
                                                 const float* __restrict__ bv) {
    const int z = blockIdx.z;
    const __nv_bfloat16* Wh = g_wh + (size_t)z * EMB * EMB;
    const __nv_bfloat16* Wl = g_wl + (size_t)z * EMB * EMB;
    const float* bias = (z == 0) ? bq : (z == 1) ? bk : bv;
    float* C          = (z == 0) ? g_q : (z == 1) ? g_k : g_v;
    const float scale = (z == 0) ? 0.125f : 1.0f;   // hd^-0.5
    mm_gemm_body(g_xh, g_xl, Wh, Wl, bias, C, scale,
                 blockIdx.y * 128, blockIdx.x * 128);
}

__global__ __launch_bounds__(256, 1) void mm_out(const float* __restrict__ bo,
                                                 float* __restrict__ out) {
    mm_gemm_body(g_ah, g_al, g_wh + (size_t)3 * EMB * EMB,
                 g_wl + (size_t)3 * EMB * EMB, bo, out, 1.0f,
                 blockIdx.y * 128, blockIdx.x * 128);
}

// ---------------- RoPE + transpose to head layout --------------------------
__global__ __launch_bounds__(256) void rope_kernel() {
    const int which = blockIdx.z;
    const float* src = (which == 0) ? g_q  : (which == 1) ? g_k  : g_v;
    float*       dst = (which == 0) ? g_qh : (which == 1) ? g_kh : g_vh;

    const int idx = blockIdx.x * 256 + threadIdx.x;
    const int d = idx & (HD - 1);
    const int s = (idx >> 6) & (SEQ - 1);
    const int g = idx >> 17;
    const int b  = g >> 4;
    const int hh = g & 15;

    const size_t so = ((size_t)s * BATCH + b) * EMB + hh * HD;
    const float x = src[so + d];
    float outv;
    if (which == 2) {
        outv = x;
    } else {
        const int i = d & 31;
        const float inv_f = powf(10000.f, -(float)(2 * i) * (1.f / 64.f));
        const float ang = (float)s * inv_f;
        float sn, c;
        sincosf(ang, &sn, &c);
        const float partner = src[so + ((d < 32) ? d + 32 : d - 32)];
        outv = fmaf(x, c, ((d < 32) ? -partner : partner) * sn);
    }
    dst[idx] = outv;
}

// ---------------- Flash attention (unchanged) -------------------------------
#define BQ  128
#define BKV 32

__global__ __launch_bounds__(BQ) void attn_kernel() {
    __shared__ float Ks[BKV][HD];
    __shared__ float Vs[BKV][HD];
    __shared__ float Ss[BKV][BQ];

    const int g   = blockIdx.y;
    const int tid = threadIdx.x;
    const int s   = blockIdx.x * BQ + tid;

    const float* qptr = g_qh + ((size_t)g * SEQ + s) * HD;
    float q[HD], acc[HD];
    #pragma unroll
    for (int d = 0; d < HD; d += 4) {
        float4 t = *(const float4*)(qptr + d);
        q[d] = t.x; q[d + 1] = t.y; q[d + 2] = t.z; q[d + 3] = t.w;
        acc[d] = 0.f; acc[d + 1] = 0.f; acc[d + 2] = 0.f; acc[d + 3] = 0.f;
    }
    float m = -1e30f, l = 0.f;

    const float* kb = g_kh + (size_t)g * SEQ * HD;
    const float* vb = g_vh + (size_t)g * SEQ * HD;

    for (int t0 = 0; t0 < SEQ; t0 += BKV) {
        __syncthreads();
        #pragma unroll
        for (int r = 0; r < (BKV * HD) / (BQ * 4); r++) {
            const int idx = (r * BQ + tid) * 4;
            *(float4*)((float*)Ks + idx) = *(const float4*)(kb + (size_t)t0 * HD + idx);
            *(float4*)((float*)Vs + idx) = *(const float4*)(vb + (size_t)t0 * HD + idx);
        }
        __syncthreads();

        float tmax = -1e30f;
        for (int j = 0; j < BKV; j++) {
            float sum = 0.f;
            #pragma unroll
            for (int d = 0; d < HD; d += 4) {
                float4 kv = *(const float4*)&Ks[j][d];
                sum += q[d] * kv.x + q[d + 1] * kv.y + q[d + 2] * kv.z + q[d + 3] * kv.w;
            }
            Ss[j][tid] = sum;
            tmax = fmaxf(tmax, sum);
        }

        const float mnew = fmaxf(m, tmax);
        const float corr = __expf(m - mnew);
        l *= corr;
        #pragma unroll
        for (int d = 0; d < HD; d++) acc[d] *= corr;

        for (int j = 0; j < BKV; j++) {
            const float p = __expf(Ss[j][tid] - mnew);
            l += p;
            #pragma unroll
            for (int d = 0; d < HD; d += 4) {
                float4 vv = *(const float4*)&Vs[j][d];
                acc[d]     = fmaf(p, vv.x, acc[d]);
                acc[d + 1] = fmaf(p, vv.y, acc[d + 1]);
                acc[d + 2] = fmaf(p, vv.z, acc[d + 2]);
                acc[d + 3] = fmaf(p, vv.w, acc[d + 3]);
            }
        }
        m = mnew;
    }

    const int b  = g / NH;
    const int hh = g % NH;
    float* o = g_attn + ((size_t)s * BATCH + b) * EMB + hh * HD;
    const float invl = 1.f / l;
    #pragma unroll
    for (int d = 0; d < HD; d += 4) {
        float4 w;
        w.x = acc[d] * invl;     w.y = acc[d + 1] * invl;
        w.z = acc[d + 2] * invl; w.w = acc[d + 3] * invl;
        *(float4*)(o + d) = w;
    }
}

// ---------------- launch ----------------------------------------------------
extern "C" void kernel_launch(void* const* d_in, const int* in_sizes, int n_in,
                              void* d_out, int out_size) {
    (void)in_sizes; (void)n_in; (void)out_size;
    const float* query = (const float*)d_in[0];
    const float* Wq    = (const float*)d_in[1];
    const float* bq    = (const float*)d_in[2];
    const float* Wk    = (const float*)d_in[3];
    const float* bk    = (const float*)d_in[4];
    const float* Wv    = (const float*)d_in[5];
    const float* bv    = (const float*)d_in[6];
    const float* Wo    = (const float*)d_in[7];
    const float* bo    = (const float*)d_in[8];
    float* out = (float*)d_out;

    __nv_bfloat16 *xh, *xl, *ah, *al;
    cudaGetSymbolAddress((void**)&xh, g_xh);
    cudaGetSymbolAddress((void**)&xl, g_xl);
    cudaGetSymbolAddress((void**)&ah, g_ah);
    cudaGetSymbolAddress((void**)&al, g_al);
    float* attn;
    cudaGetSymbolAddress((void**)&attn, g_attn);

    // 0) fp32 -> bf16 hi/lo splits (X and weights)
    cvt_split<<<MROWS * EMB / 1024, 256>>>(query, xh, xl);
    dim3 gw(EMB * EMB / 1024, 1, 4);
    cvt_w<<<gw, 256>>>(Wq, Wk, Wv, Wo);

    // 1) fused QKV projection (split-bf16 mma.sync, fp32 accum)
    dim3 gq(EMB / 128, MROWS / 128, 3);     // (8, 32, 3)
    mm_qkv<<<gq, 256>>>(bq, bk, bv);

    // 2) RoPE + transpose to head layout
    dim3 gr((NHEADS * SEQ * HD) / 256, 1, 3);
    rope_kernel<<<gr, 256>>>();

    // 3) flash attention
    dim3 ga(SEQ / BQ, NHEADS);
    attn_kernel<<<ga, BQ>>>();

    // 4) split attn output, then output projection
    cvt_split<<<MROWS * EMB / 1024, 256>>>(attn, ah, al);
    dim3 go(EMB / 128, MROWS / 128);        // (8, 32)
    mm_out<<<go, 256>>>(bo, out);
}

// round 5
// speedup vs baseline: 2.9726x; 2.4933x over previous
#include <cuda_runtime.h>
#include <cuda_bf16.h>
#include <cstdint>
#include <math.h>

// Problem constants (fixed shapes)
#define SEQ    2048
#define BATCH  2
#define EMB    1024
#define NH     16
#define HD     64
#define NHEADS (BATCH * NH)     // 32 flattened heads
#define MROWS  (SEQ * BATCH)    // 4096 token rows
#define L2E    1.4426950408889634f

// ---------------- scratch (static device memory; no allocs) ----------------
__device__ float g_q[MROWS * EMB];          // QKV projection outputs (fp32)
__device__ float g_k[MROWS * EMB];
__device__ float g_v[MROWS * EMB];

// split bf16 head-layout tensors [g][s][d]
__device__ __nv_bfloat16 g_qsh[NHEADS * SEQ * HD];
__device__ __nv_bfloat16 g_qsl[NHEADS * SEQ * HD];
__device__ __nv_bfloat16 g_ksh[NHEADS * SEQ * HD];
__device__ __nv_bfloat16 g_ksl[NHEADS * SEQ * HD];
__device__ __nv_bfloat16 g_vsh[NHEADS * SEQ * HD];
__device__ __nv_bfloat16 g_vsl[NHEADS * SEQ * HD];

// bf16 hi/lo split GEMM operands
__device__ __nv_bfloat16 g_xh[MROWS * EMB];
__device__ __nv_bfloat16 g_xl[MROWS * EMB];
__device__ __nv_bfloat16 g_wh[4 * EMB * EMB];   // Wq, Wk, Wv, Wo
__device__ __nv_bfloat16 g_wl[4 * EMB * EMB];
__device__ __nv_bfloat16 g_ah[MROWS * EMB];     // attention out (split)
__device__ __nv_bfloat16 g_al[MROWS * EMB];

// ======================= helpers ===========================================
__device__ __forceinline__ uint32_t smem_to_u32(const void* smem_ptr) {
    uint32_t addr;
    asm("{ .reg .u64 tmp; cvta.to.shared.u64 tmp, %1; cvt.u32.u64 %0, tmp; }"
        : "=r"(addr) : "l"(smem_ptr));
    return addr;
}
__device__ __forceinline__ void ldm_x4(uint32_t* r, uint32_t addr) {
    asm volatile("ldmatrix.sync.aligned.m8n8.x4.shared.b16 {%0,%1,%2,%3}, [%4];"
                 : "=r"(r[0]), "=r"(r[1]), "=r"(r[2]), "=r"(r[3]) : "r"(addr));
}
__device__ __forceinline__ void ldm_x4_t(uint32_t* r, uint32_t addr) {
    asm volatile("ldmatrix.sync.aligned.m8n8.x4.trans.shared.b16 {%0,%1,%2,%3}, [%4];"
                 : "=r"(r[0]), "=r"(r[1]), "=r"(r[2]), "=r"(r[3]) : "r"(addr));
}
__device__ __forceinline__ void ldm_x2(uint32_t* r, uint32_t addr) {
    asm volatile("ldmatrix.sync.aligned.m8n8.x2.shared.b16 {%0,%1}, [%2];"
                 : "=r"(r[0]), "=r"(r[1]) : "r"(addr));
}
__device__ __forceinline__ void mma_bf16(float* d, const uint32_t* a, const uint32_t* b) {
    asm volatile(
        "mma.sync.aligned.m16n8k16.row.col.f32.bf16.bf16.f32 "
        "{%0,%1,%2,%3}, {%4,%5,%6,%7}, {%8,%9}, {%0,%1,%2,%3};"
        : "+f"(d[0]), "+f"(d[1]), "+f"(d[2]), "+f"(d[3])
        : "r"(a[0]), "r"(a[1]), "r"(a[2]), "r"(a[3]), "r"(b[0]), "r"(b[1]));
}
__device__ __forceinline__ void cp_async16(uint32_t dst, const void* src) {
    asm volatile("cp.async.ca.shared.global [%0], [%1], 16;" :: "r"(dst), "l"(src));
}
__device__ __forceinline__ void cp_commit() {
    asm volatile("cp.async.commit_group;" ::: "memory");
}
template <int N>
__device__ __forceinline__ void cp_wait() {
    asm volatile("cp.async.wait_group %0;" :: "n"(N) : "memory");
}
__device__ __forceinline__ float ex2(float x) {
    float r; asm("ex2.approx.f32 %0, %1;" : "=f"(r) : "f"(x)); return r;
}
__device__ __forceinline__ uint32_t b2u(__nv_bfloat162 h) {
    return *reinterpret_cast<uint32_t*>(&h);
}

// ======================= fp32 -> bf16 hi/lo conversion ======================
__device__ __forceinline__ void split4(const float4 x, __nv_bfloat162* hi2,
                                       __nv_bfloat162* lo2, size_t i2) {
    __nv_bfloat16 h0 = __float2bfloat16(x.x);
    __nv_bfloat16 h1 = __float2bfloat16(x.y);
    __nv_bfloat16 h2 = __float2bfloat16(x.z);
    __nv_bfloat16 h3 = __float2bfloat16(x.w);
    hi2[i2]     = __nv_bfloat162(h0, h1);
    hi2[i2 + 1] = __nv_bfloat162(h2, h3);
    lo2[i2]     = __nv_bfloat162(__float2bfloat16(x.x - __bfloat162float(h0)),
                                 __float2bfloat16(x.y - __bfloat162float(h1)));
    lo2[i2 + 1] = __nv_bfloat162(__float2bfloat16(x.z - __bfloat162float(h2)),
                                 __float2bfloat16(x.w - __bfloat162float(h3)));
}

__global__ __launch_bounds__(256) void cvt_split(const float* __restrict__ src,
                                                 __nv_bfloat16* __restrict__ hi,
                                                 __nv_bfloat16* __restrict__ lo) {
    const size_t i4 = (size_t)blockIdx.x * 256 + threadIdx.x;
    float4 x = ((const float4*)src)[i4];
    split4(x, (__nv_bfloat162*)hi, (__nv_bfloat162*)lo, i4 * 2);
}

__global__ __launch_bounds__(256) void cvt_w(const float* __restrict__ Wq,
                                             const float* __restrict__ Wk,
                                             const float* __restrict__ Wv,
                                             const float* __restrict__ Wo) {
    const int z = blockIdx.z;
    const float* src = (z == 0) ? Wq : (z == 1) ? Wk : (z == 2) ? Wv : Wo;
    const size_t base4 = (size_t)z * (EMB * EMB / 4);
    const size_t i4 = base4 + (size_t)blockIdx.x * 256 + threadIdx.x;
    float4 x = ((const float4*)src)[(size_t)blockIdx.x * 256 + threadIdx.x];
    split4(x, (__nv_bfloat162*)g_wh, (__nv_bfloat162*)g_wl, i4 * 2);
}

// ======================= mma.sync split-bf16 GEMM (from R3) =================
#define MM_BK       16
#define TILE_STRIDE 48
#define TILE_SZ     (128 * TILE_STRIDE)
#define STG_SZ      (4 * TILE_SZ)
#define N_ITERS     (EMB / MM_BK)

__device__ __forceinline__ void mm_gemm_body(const __nv_bfloat16* __restrict__ Ah,
                                             const __nv_bfloat16* __restrict__ Al,
                                             const __nv_bfloat16* __restrict__ Wh,
                                             const __nv_bfloat16* __restrict__ Wl,
                                             const float* __restrict__ bias,
                                             float* __restrict__ C, float scale,
                                             int m0, int n0)
{
    __shared__ __align__(16) char sm[2 * STG_SZ];   // 49152 B
    const uint32_t smb = smem_to_u32(sm);

    const int tid  = threadIdx.x;
    const int lane = tid & 31;
    const int wid  = tid >> 5;
    const int wm   = wid >> 1;
    const int wn   = wid & 1;

    const int lrow  = tid >> 1;
    const int lhalf = tid & 1;
    const uint32_t st_off = (uint32_t)(lrow * TILE_STRIDE + lhalf * 16);

    const __nv_bfloat16* pAh = Ah + (size_t)(m0 + lrow) * EMB + lhalf * 8;
    const __nv_bfloat16* pAl = Al + (size_t)(m0 + lrow) * EMB + lhalf * 8;
    const __nv_bfloat16* pWh = Wh + (size_t)(n0 + lrow) * EMB + lhalf * 8;
    const __nv_bfloat16* pWl = Wl + (size_t)(n0 + lrow) * EMB + lhalf * 8;

    float acc[2][8][4];
    #pragma unroll
    for (int mi = 0; mi < 2; mi++)
        #pragma unroll
        for (int ni = 0; ni < 8; ni++)
            #pragma unroll
            for (int j = 0; j < 4; j++) acc[mi][ni][j] = 0.f;

    uint4 vAh = *(const uint4*)pAh;
    uint4 vAl = *(const uint4*)pAl;
    uint4 vWh = *(const uint4*)pWh;
    uint4 vWl = *(const uint4*)pWl;

    for (int k = 0; k < N_ITERS; k++) {
        const int cur = k & 1;
        char* sb = sm + cur * STG_SZ;
        *(uint4*)(sb + 0 * TILE_SZ + st_off) = vAh;
        *(uint4*)(sb + 1 * TILE_SZ + st_off) = vAl;
        *(uint4*)(sb + 2 * TILE_SZ + st_off) = vWh;
        *(uint4*)(sb + 3 * TILE_SZ + st_off) = vWl;
        __syncthreads();

        if (k + 1 < N_ITERS) {
            const int ko = (k + 1) * MM_BK;
            vAh = *(const uint4*)(pAh + ko);
            vAl = *(const uint4*)(pAl + ko);
            vWh = *(const uint4*)(pWh + ko);
            vWl = *(const uint4*)(pWl + ko);
        }

        const uint32_t tb = smb + cur * STG_SZ;
        uint32_t aH[2][4], aL[2][4], bH[8][2], bL[8][2];
        #pragma unroll
        for (int mi = 0; mi < 2; mi++) {
            const uint32_t row = wm * 32 + mi * 16 + (lane & 15);
            const uint32_t addr = tb + row * TILE_STRIDE + (lane >> 4) * 16;
            ldm_x4(aH[mi], addr);
            ldm_x4(aL[mi], addr + TILE_SZ);
        }
        #pragma unroll
        for (int ni = 0; ni < 8; ni++) {
            const uint32_t row = wn * 64 + ni * 8 + (lane & 7);
            const uint32_t addr = tb + 2 * TILE_SZ + row * TILE_STRIDE + ((lane >> 3) & 1) * 16;
            ldm_x2(bH[ni], addr);
            ldm_x2(bL[ni], addr + TILE_SZ);
        }

        #pragma unroll
        for (int mi = 0; mi < 2; mi++)
            #pragma unroll
            for (int ni = 0; ni < 8; ni++) {
                mma_bf16(acc[mi][ni], aH[mi], bH[ni]);
                mma_bf16(acc[mi][ni], aH[mi], bL[ni]);
                mma_bf16(acc[mi][ni], aL[mi], bH[ni]);
            }
        __syncthreads();
    }

    #pragma unroll
    for (int mi = 0; mi < 2; mi++) {
        #pragma unroll
        for (int ni = 0; ni < 8; ni++) {
            const int r  = m0 + wm * 32 + mi * 16 + (lane >> 2);
            const int c  = n0 + wn * 64 + ni * 8 + (lane & 3) * 2;
            float2 v0, v1;
            v0.x = (acc[mi][ni][0] + bias[c])     * scale;
            v0.y = (acc[mi][ni][1] + bias[c + 1]) * scale;
            v1.x = (acc[mi][ni][2] + bias[c])     * scale;
            v1.y = (acc[mi][ni][3] + bias[c + 1]) * scale;
            *(float2*)(C + (size_t)r * EMB + c)       = v0;
            *(float2*)(C + (size_t)(r + 8) * EMB + c) = v1;
        }
    }
}

__global__ __launch_bounds__(256, 1) void mm_qkv(const float* __restrict__ bq,
                                                 const float* __restrict__ bk,
                                                 const float* __restrict__ bv) {
    const int z = blockIdx.z;
    const __nv_bfloat16* Wh = g_wh + (size_t)z * EMB * EMB;
    const __nv_bfloat16* Wl = g_wl + (size_t)z * EMB * EMB;
    const float* bias = (z == 0) ? bq : (z == 1) ? bk : bv;
    float* C          = (z == 0) ? g_q : (z == 1) ? g_k : g_v;
    const float scale = (z == 0) ? 0.125f : 1.0f;   // hd^-0.5
    mm_gemm_body(g_xh, g_xl, Wh, Wl, bias, C, scale,
                 blockIdx.y * 128, blockIdx.x * 128);
}

__global__ __launch_bounds__(256, 1) void mm_out(const float* __restrict__ bo,
                                                 float* __restrict__ out) {
    mm_gemm_body(g_ah, g_al, g_wh + (size_t)3 * EMB * EMB,
                 g_wl + (size_t)3 * EMB * EMB, bo, out, 1.0f,
                 blockIdx.y * 128, blockIdx.x * 128);
}

// ---------------- RoPE + transpose to head layout (split bf16 out) ----------
__global__ __launch_bounds__(256) void rope_split() {
    const int which = blockIdx.z;
    const float* src = (which == 0) ? g_q : (which == 1) ? g_k : g_v;
    __nv_bfloat16* hi = (which == 0) ? g_qsh : (which == 1) ? g_ksh : g_vsh;
    __nv_bfloat16* lo = (which == 0) ? g_qsl : (which == 1) ? g_ksl : g_vsl;

    const int idx = blockIdx.x * 256 + threadIdx.x;
    const int d = idx & (HD - 1);
    const int s = (idx >> 6) & (SEQ - 1);
    const int g = idx >> 17;
    const int b  = g >> 4;
    const int hh = g & 15;

    const size_t so = ((size_t)s * BATCH + b) * EMB + hh * HD;
    const float x = src[so + d];
    float outv;
    if (which == 2) {
        outv = x;
    } else {
        const int i = d & 31;
        const float inv_f = powf(10000.f, -(float)(2 * i) * (1.f / 64.f));
        const float ang = (float)s * inv_f;
        float sn, c;
        sincosf(ang, &sn, &c);
        const float partner = src[so + ((d < 32) ? d + 32 : d - 32)];
        outv = fmaf(x, c, ((d < 32) ? -partner : partner) * sn);
    }
    const __nv_bfloat16 h = __float2bfloat16(outv);
    hi[idx] = h;
    lo[idx] = __float2bfloat16(outv - __bfloat162float(h));
}

// ================= tensor-core flash attention (split bf16) =================
// CTA: (head g, 128 q rows). 8 warps x m16 rows. KV tiles of 64, double-buffer
// in dynamic smem via cp.async. Q frags in registers.
#define ABKV   64
#define A_RS   144                       // padded row stride bytes (64 bf16 + 8)
#define A_KT   (64 * A_RS)               // 9216 per tile
#define A_STG  (4 * A_KT)                // Kh,Kl,Vh,Vl = 36864
#define A_SMEM (2 * A_STG)               // 73728
#define A_NT   (SEQ / ABKV)              // 32

__device__ __forceinline__ void kv_load(uint32_t stb, int g, int kv0, int tid) {
    #pragma unroll
    for (int i = 0; i < 8; i++) {
        const int gid  = i * 256 + tid;
        const int tile = gid >> 9;
        const int gi   = gid & 511;
        const int row  = gi >> 3, ch = gi & 7;
        const __nv_bfloat16* base =
            (tile == 0) ? g_ksh : (tile == 1) ? g_ksl : (tile == 2) ? g_vsh : g_vsl;
        const void* src = base + ((size_t)g * SEQ + kv0 + row) * HD + ch * 8;
        cp_async16(stb + tile * A_KT + row * A_RS + ch * 16, src);
    }
}

__global__ __launch_bounds__(256, 1) void attn_mma() {
    extern __shared__ __align__(16) char dynsm[];
    const uint32_t smb = smem_to_u32(dynsm);
    const int g  = blockIdx.y;
    const int qb = blockIdx.x;
    const int tid = threadIdx.x, lane = tid & 31, wid = tid >> 5;

    // ---- stage Q (hi then lo) through smem -> register fragments ----
    uint32_t qhf[4][4], qlf[4][4];
    {
        const __nv_bfloat16* qsrc[2] = { g_qsh, g_qsl };
        for (int pass = 0; pass < 2; pass++) {
            #pragma unroll
            for (int i = 0; i < 4; i++) {
                const int gid = i * 256 + tid;
                const int row = gid >> 3, ch = gid & 7;
                *(uint4*)(dynsm + row * A_RS + ch * 16) =
                    *(const uint4*)(qsrc[pass] + ((size_t)g * SEQ + qb * 128 + row) * HD + ch * 8);
            }
            __syncthreads();
            #pragma unroll
            for (int kt = 0; kt < 4; kt++) {
                const uint32_t addr = smb + (wid * 16 + (lane & 15)) * A_RS
                                    + kt * 32 + (lane >> 4) * 16;
                ldm_x4(pass ? qlf[kt] : qhf[kt], addr);
            }
            __syncthreads();
        }
    }

    float O[8][4];
    #pragma unroll
    for (int nd = 0; nd < 8; nd++)
        #pragma unroll
        for (int j = 0; j < 4; j++) O[nd][j] = 0.f;
    float m_lo = -1e30f, m_hi = -1e30f, l_lo = 0.f, l_hi = 0.f;

    // preload KV tile 0 into stage 0
    kv_load(smb, g, 0, tid);
    cp_commit();

    for (int t = 0; t < A_NT; t++) {
        __syncthreads();                       // everyone done with stage (t+1)&1
        if (t + 1 < A_NT) {
            kv_load(smb + ((t + 1) & 1) * A_STG, g, (t + 1) * ABKV, tid);
            cp_commit();
            cp_wait<1>();
        } else {
            cp_wait<0>();
        }
        __syncthreads();
        const uint32_t stb = smb + (t & 1) * A_STG;

        // ---- S = Q K^T (3-way split) ----
        float S[8][4];
        #pragma unroll
        for (int nt = 0; nt < 8; nt++)
            #pragma unroll
            for (int j = 0; j < 4; j++) S[nt][j] = 0.f;
        #pragma unroll
        for (int kt = 0; kt < 4; kt++) {
            #pragma unroll
            for (int nt = 0; nt < 8; nt++) {
                uint32_t bh[2], bl[2];
                const uint32_t addr = stb + (nt * 8 + (lane & 7)) * A_RS
                                    + kt * 32 + ((lane >> 3) & 1) * 16;
                ldm_x2(bh, addr);
                ldm_x2(bl, addr + A_KT);
                mma_bf16(S[nt], qhf[kt], bh);
                mma_bf16(S[nt], qhf[kt], bl);
                mma_bf16(S[nt], qlf[kt], bh);
            }
        }

        // ---- online softmax (rows r = lane>>2 (lo) and r+8 (hi)) ----
        float tm_lo = -1e30f, tm_hi = -1e30f;
        #pragma unroll
        for (int nt = 0; nt < 8; nt++) {
            tm_lo = fmaxf(tm_lo, fmaxf(S[nt][0], S[nt][1]));
            tm_hi = fmaxf(tm_hi, fmaxf(S[nt][2], S[nt][3]));
        }
        tm_lo = fmaxf(tm_lo, __shfl_xor_sync(0xffffffffu, tm_lo, 1));
        tm_lo = fmaxf(tm_lo, __shfl_xor_sync(0xffffffffu, tm_lo, 2));
        tm_hi = fmaxf(tm_hi, __shfl_xor_sync(0xffffffffu, tm_hi, 1));
        tm_hi = fmaxf(tm_hi, __shfl_xor_sync(0xffffffffu, tm_hi, 2));

        const float mn_lo = fmaxf(m_lo, tm_lo);
        const float mn_hi = fmaxf(m_hi, tm_hi);
        const float corr_lo = ex2((m_lo - mn_lo) * L2E);
        const float corr_hi = ex2((m_hi - mn_hi) * L2E);
        m_lo = mn_lo; m_hi = mn_hi;
        l_lo *= corr_lo; l_hi *= corr_hi;
        #pragma unroll
        for (int nd = 0; nd < 8; nd++) {
            O[nd][0] *= corr_lo; O[nd][1] *= corr_lo;
            O[nd][2] *= corr_hi; O[nd][3] *= corr_hi;
        }
        const float mb_lo = mn_lo * L2E, mb_hi = mn_hi * L2E;

        uint32_t aPh[4][4], aPl[4][4];
        #pragma unroll
        for (int kt = 0; kt < 4; kt++) {
            #pragma unroll
            for (int half = 0; half < 2; half++) {
                const int nt = 2 * kt + half;
                const float p0 = ex2(fmaf(S[nt][0], L2E, -mb_lo));
                const float p1 = ex2(fmaf(S[nt][1], L2E, -mb_lo));
                const float p2 = ex2(fmaf(S[nt][2], L2E, -mb_hi));
                const float p3 = ex2(fmaf(S[nt][3], L2E, -mb_hi));
                l_lo += p0 + p1; l_hi += p2 + p3;
                __nv_bfloat162 h01 = __floats2bfloat162_rn(p0, p1);
                __nv_bfloat162 h23 = __floats2bfloat162_rn(p2, p3);
                aPh[kt][half * 2 + 0] = b2u(h01);
                aPh[kt][half * 2 + 1] = b2u(h23);
                __nv_bfloat162 l01 = __floats2bfloat162_rn(
                    p0 - __bfloat162float(h01.x), p1 - __bfloat162float(h01.y));
                __nv_bfloat162 l23 = __floats2bfloat162_rn(
                    p2 - __bfloat162float(h23.x), p3 - __bfloat162float(h23.y));
                aPl[kt][half * 2 + 0] = b2u(l01);
                aPl[kt][half * 2 + 1] = b2u(l23);
            }
        }

        // ---- O += P V (3-way split); V B-frags via ldmatrix.trans ----
        #pragma unroll
        for (int kt = 0; kt < 4; kt++) {
            #pragma unroll
            for (int ndp = 0; ndp < 4; ndp++) {
                uint32_t vh[4], vl[4];
                const uint32_t addr = stb + 2 * A_KT
                                    + (kt * 16 + (lane & 15)) * A_RS
                                    + ndp * 32 + (lane >> 4) * 16;
                ldm_x4_t(vh, addr);
                ldm_x4_t(vl, addr + A_KT);
                mma_bf16(O[2 * ndp],     aPh[kt], &vh[0]);
                mma_bf16(O[2 * ndp],     aPh[kt], &vl[0]);
                mma_bf16(O[2 * ndp],     aPl[kt], &vh[0]);
                mma_bf16(O[2 * ndp + 1], aPh[kt], &vh[2]);
                mma_bf16(O[2 * ndp + 1], aPh[kt], &vl[2]);
                mma_bf16(O[2 * ndp + 1], aPl[kt], &vh[2]);
            }
        }
    }

    // ---- finalize: normalize, split hi/lo, write token-row layout ----
    l_lo += __shfl_xor_sync(0xffffffffu, l_lo, 1);
    l_lo += __shfl_xor_sync(0xffffffffu, l_lo, 2);
    l_hi += __shfl_xor_sync(0xffffffffu, l_hi, 1);
    l_hi += __shfl_xor_sync(0xffffffffu, l_hi, 2);
    const float il_lo = 1.f / l_lo, il_hi = 1.f / l_hi;

    const int b  = g >> 4;
    const int hh = g & 15;
    const int r0 = qb * 128 + wid * 16 + (lane >> 2);     // lo rows
    #pragma unroll
    for (int nd = 0; nd < 8; nd++) {
        const int col = hh * HD + nd * 8 + (lane & 3) * 2;
        // lo row
        {
            const float v0 = O[nd][0] * il_lo, v1 = O[nd][1] * il_lo;
            __nv_bfloat162 h = __floats2bfloat162_rn(v0, v1);
            __nv_bfloat162 l = __floats2bfloat162_rn(v0 - __bfloat162float(h.x),
                                                     v1 - __bfloat162float(h.y));
            const size_t off = (size_t)(r0 * BATCH + b) * EMB + col;
            *(__nv_bfloat162*)(g_ah + off) = h;
            *(__nv_bfloat162*)(g_al + off) = l;
        }
        // hi row (+8)
        {
            const float v0 = O[nd][2] * il_hi, v1 = O[nd][3] * il_hi;
            __nv_bfloat162 h = __floats2bfloat162_rn(v0, v1);
            __nv_bfloat162 l = __floats2bfloat162_rn(v0 - __bfloat162float(h.x),
                                                     v1 - __bfloat162float(h.y));
            const size_t off = (size_t)((r0 + 8) * BATCH + b) * EMB + col;
            *(__nv_bfloat162*)(g_ah + off) = h;
            *(__nv_bfloat162*)(g_al + off) = l;
        }
    }
}

// ---------------- launch ----------------------------------------------------
extern "C" void kernel_launch(void* const* d_in, const int* in_sizes, int n_in,
                              void* d_out, int out_size) {
    (void)in_sizes; (void)n_in; (void)out_size;
    const float* query = (const float*)d_in[0];
    const float* bq    = (const float*)d_in[2];
    const float* bk    = (const float*)d_in[4];
    const float* bv    = (const float*)d_in[6];
    const float* bo    = (const float*)d_in[8];
    float* out = (float*)d_out;

    cudaFuncSetAttribute(attn_mma, cudaFuncAttributeMaxDynamicSharedMemorySize, A_SMEM);

    __nv_bfloat16* xh; __nv_bfloat16* xl;
    cudaGetSymbolAddress((void**)&xh, g_xh);
    cudaGetSymbolAddress((void**)&xl, g_xl);

    // 0) fp32 -> bf16 hi/lo splits (X and weights)
    cvt_split<<<MROWS * EMB / 1024, 256>>>(query, xh, xl);
    dim3 gw(EMB * EMB / 1024, 1, 4);
    cvt_w<<<gw, 256>>>((const float*)d_in[1], (const float*)d_in[3],
                       (const float*)d_in[5], (const float*)d_in[7]);

    // 1) fused QKV projection (split-bf16 mma.sync, fp32 accum)
    dim3 gq(EMB / 128, MROWS / 128, 3);
    mm_qkv<<<gq, 256>>>(bq, bk, bv);

    // 2) RoPE + head layout + hi/lo split
    dim3 gr((NHEADS * SEQ * HD) / 256, 1, 3);
    rope_split<<<gr, 256>>>();

    // 3) tensor-core flash attention (writes g_ah/g_al directly)
    dim3 ga(SEQ / 128, NHEADS);
    attn_mma<<<ga, 256, A_SMEM>>>();

    // 4) output projection
    dim3 go(EMB / 128, MROWS / 128);
    mm_out<<<go, 256>>>(bo, out);
}

// round 6
// speedup vs baseline: 3.2459x; 1.0919x over previous
#include <cuda_runtime.h>
#include <cuda_bf16.h>
#include <cstdint>
#include <math.h>

// Problem constants (fixed shapes)
#define SEQ    2048
#define BATCH  2
#define EMB    1024
#define NH     16
#define HD     64
#define NHEADS (BATCH * NH)     // 32 flattened heads
#define MROWS  (SEQ * BATCH)    // 4096 token rows
#define L2E    1.4426950408889634f

// ---------------- scratch (static device memory; no allocs) ----------------
// split bf16 head-layout tensors [g][s][d]
__device__ __nv_bfloat16 g_qsh[NHEADS * SEQ * HD];
__device__ __nv_bfloat16 g_qsl[NHEADS * SEQ * HD];
__device__ __nv_bfloat16 g_ksh[NHEADS * SEQ * HD];
__device__ __nv_bfloat16 g_ksl[NHEADS * SEQ * HD];
__device__ __nv_bfloat16 g_vsh[NHEADS * SEQ * HD];
__device__ __nv_bfloat16 g_vsl[NHEADS * SEQ * HD];

// bf16 hi/lo split GEMM operands
__device__ __nv_bfloat16 g_xh[MROWS * EMB];
__device__ __nv_bfloat16 g_xl[MROWS * EMB];
__device__ __nv_bfloat16 g_wh[4 * EMB * EMB];   // Wq, Wk, Wv, Wo
__device__ __nv_bfloat16 g_wl[4 * EMB * EMB];
__device__ __nv_bfloat16 g_ah[MROWS * EMB];     // attention out (split)
__device__ __nv_bfloat16 g_al[MROWS * EMB];

// rope cos/sin table: [s][i] i in [0,32), .x = cos, .y = sin
__device__ float2 g_rope[SEQ * 32];

// ======================= helpers ===========================================
__device__ __forceinline__ uint32_t smem_to_u32(const void* smem_ptr) {
    uint32_t addr;
    asm("{ .reg .u64 tmp; cvta.to.shared.u64 tmp, %1; cvt.u32.u64 %0, tmp; }"
        : "=r"(addr) : "l"(smem_ptr));
    return addr;
}
__device__ __forceinline__ void ldm_x4(uint32_t* r, uint32_t addr) {
    asm volatile("ldmatrix.sync.aligned.m8n8.x4.shared.b16 {%0,%1,%2,%3}, [%4];"
                 : "=r"(r[0]), "=r"(r[1]), "=r"(r[2]), "=r"(r[3]) : "r"(addr));
}
__device__ __forceinline__ void ldm_x4_t(uint32_t* r, uint32_t addr) {
    asm volatile("ldmatrix.sync.aligned.m8n8.x4.trans.shared.b16 {%0,%1,%2,%3}, [%4];"
                 : "=r"(r[0]), "=r"(r[1]), "=r"(r[2]), "=r"(r[3]) : "r"(addr));
}
__device__ __forceinline__ void ldm_x2(uint32_t* r, uint32_t addr) {
    asm volatile("ldmatrix.sync.aligned.m8n8.x2.shared.b16 {%0,%1}, [%2];"
                 : "=r"(r[0]), "=r"(r[1]) : "r"(addr));
}
__device__ __forceinline__ void mma_bf16(float* d, const uint32_t* a, const uint32_t* b) {
    asm volatile(
        "mma.sync.aligned.m16n8k16.row.col.f32.bf16.bf16.f32 "
        "{%0,%1,%2,%3}, {%4,%5,%6,%7}, {%8,%9}, {%0,%1,%2,%3};"
        : "+f"(d[0]), "+f"(d[1]), "+f"(d[2]), "+f"(d[3])
        : "r"(a[0]), "r"(a[1]), "r"(a[2]), "r"(a[3]), "r"(b[0]), "r"(b[1]));
}
__device__ __forceinline__ void cp_async16(uint32_t dst, const void* src) {
    asm volatile("cp.async.ca.shared.global [%0], [%1], 16;" :: "r"(dst), "l"(src));
}
__device__ __forceinline__ void cp_commit() {
    asm volatile("cp.async.commit_group;" ::: "memory");
}
template <int N>
__device__ __forceinline__ void cp_wait() {
    asm volatile("cp.async.wait_group %0;" :: "n"(N) : "memory");
}
__device__ __forceinline__ float ex2(float x) {
    float r; asm("ex2.approx.f32 %0, %1;" : "=f"(r) : "f"(x)); return r;
}
__device__ __forceinline__ uint32_t b2u(__nv_bfloat162 h) {
    return *reinterpret_cast<uint32_t*>(&h);
}

// ======================= fp32 -> bf16 hi/lo conversion ======================
__device__ __forceinline__ void split4(const float4 x, __nv_bfloat162* hi2,
                                       __nv_bfloat162* lo2, size_t i2) {
    __nv_bfloat16 h0 = __float2bfloat16(x.x);
    __nv_bfloat16 h1 = __float2bfloat16(x.y);
    __nv_bfloat16 h2 = __float2bfloat16(x.z);
    __nv_bfloat16 h3 = __float2bfloat16(x.w);
    hi2[i2]     = __nv_bfloat162(h0, h1);
    hi2[i2 + 1] = __nv_bfloat162(h2, h3);
    lo2[i2]     = __nv_bfloat162(__float2bfloat16(x.x - __bfloat162float(h0)),
                                 __float2bfloat16(x.y - __bfloat162float(h1)));
    lo2[i2 + 1] = __nv_bfloat162(__float2bfloat16(x.z - __bfloat162float(h2)),
                                 __float2bfloat16(x.w - __bfloat162float(h3)));
}

__global__ __launch_bounds__(256) void cvt_split(const float* __restrict__ src,
                                                 __nv_bfloat16* __restrict__ hi,
                                                 __nv_bfloat16* __restrict__ lo) {
    const size_t i4 = (size_t)blockIdx.x * 256 + threadIdx.x;
    float4 x = ((const float4*)src)[i4];
    split4(x, (__nv_bfloat162*)hi, (__nv_bfloat162*)lo, i4 * 2);
}

__global__ __launch_bounds__(256) void cvt_w(const float* __restrict__ Wq,
                                             const float* __restrict__ Wk,
                                             const float* __restrict__ Wv,
                                             const float* __restrict__ Wo) {
    const int z = blockIdx.z;
    const float* src = (z == 0) ? Wq : (z == 1) ? Wk : (z == 2) ? Wv : Wo;
    const size_t base4 = (size_t)z * (EMB * EMB / 4);
    const size_t i4 = base4 + (size_t)blockIdx.x * 256 + threadIdx.x;
    float4 x = ((const float4*)src)[(size_t)blockIdx.x * 256 + threadIdx.x];
    split4(x, (__nv_bfloat162*)g_wh, (__nv_bfloat162*)g_wl, i4 * 2);
}

// rope table: cos/sin(s * 10000^(-i/32)) for i in [0,32)
__global__ __launch_bounds__(256) void rope_table() {
    const int idx = blockIdx.x * 256 + threadIdx.x;   // SEQ*32 entries
    const int s = idx >> 5, i = idx & 31;
    const float inv_f = exp2f(-(float)i * (13.287712379549449f / 32.f));
    float sn, c;
    sincosf((float)s * inv_f, &sn, &c);
    g_rope[idx] = make_float2(c, sn);
}

// ======================= mma.sync split-bf16 GEMM core ======================
#define MM_BK       16
#define TILE_STRIDE 48
#define TILE_SZ     (128 * TILE_STRIDE)
#define STG_SZ      (4 * TILE_SZ)
#define N_ITERS     (EMB / MM_BK)

// mainloop: fills acc[2][8][4] for CTA tile (m0, n0). Declared smem passed in.
__device__ __forceinline__ void mm_core(const __nv_bfloat16* __restrict__ Ah,
                                        const __nv_bfloat16* __restrict__ Al,
                                        const __nv_bfloat16* __restrict__ Wh,
                                        const __nv_bfloat16* __restrict__ Wl,
                                        int m0, int n0, char* sm,
                                        float acc[2][8][4])
{
    const uint32_t smb = smem_to_u32(sm);
    const int tid  = threadIdx.x;
    const int lane = tid & 31;
    const int wid  = tid >> 5;
    const int wm   = wid >> 1;
    const int wn   = wid & 1;

    const int lrow  = tid >> 1;
    const int lhalf = tid & 1;
    const uint32_t st_off = (uint32_t)(lrow * TILE_STRIDE + lhalf * 16);

    const __nv_bfloat16* pAh = Ah + (size_t)(m0 + lrow) * EMB + lhalf * 8;
    const __nv_bfloat16* pAl = Al + (size_t)(m0 + lrow) * EMB + lhalf * 8;
    const __nv_bfloat16* pWh = Wh + (size_t)(n0 + lrow) * EMB + lhalf * 8;
    const __nv_bfloat16* pWl = Wl + (size_t)(n0 + lrow) * EMB + lhalf * 8;

    #pragma unroll
    for (int mi = 0; mi < 2; mi++)
        #pragma unroll
        for (int ni = 0; ni < 8; ni++)
            #pragma unroll
            for (int j = 0; j < 4; j++) acc[mi][ni][j] = 0.f;

    uint4 vAh = *(const uint4*)pAh;
    uint4 vAl = *(const uint4*)pAl;
    uint4 vWh = *(const uint4*)pWh;
    uint4 vWl = *(const uint4*)pWl;

    for (int k = 0; k < N_ITERS; k++) {
        const int cur = k & 1;
        char* sb = sm + cur * STG_SZ;
        *(uint4*)(sb + 0 * TILE_SZ + st_off) = vAh;
        *(uint4*)(sb + 1 * TILE_SZ + st_off) = vAl;
        *(uint4*)(sb + 2 * TILE_SZ + st_off) = vWh;
        *(uint4*)(sb + 3 * TILE_SZ + st_off) = vWl;
        __syncthreads();

        if (k + 1 < N_ITERS) {
            const int ko = (k + 1) * MM_BK;
            vAh = *(const uint4*)(pAh + ko);
            vAl = *(const uint4*)(pAl + ko);
            vWh = *(const uint4*)(pWh + ko);
            vWl = *(const uint4*)(pWl + ko);
        }

        const uint32_t tb = smb + cur * STG_SZ;
        uint32_t aH[2][4], aL[2][4], bH[8][2], bL[8][2];
        #pragma unroll
        for (int mi = 0; mi < 2; mi++) {
            const uint32_t row = wm * 32 + mi * 16 + (lane & 15);
            const uint32_t addr = tb + row * TILE_STRIDE + (lane >> 4) * 16;
            ldm_x4(aH[mi], addr);
            ldm_x4(aL[mi], addr + TILE_SZ);
        }
        // B frags: ldmatrix.x4 fetches two n8 tiles at once
        #pragma unroll
        for (int p = 0; p < 4; p++) {
            const uint32_t row = wn * 64 + p * 16 + (lane & 7) + ((lane >> 4) << 3);
            const uint32_t addr = tb + 2 * TILE_SZ + row * TILE_STRIDE + ((lane >> 3) & 1) * 16;
            ldm_x4(&bH[2 * p][0], addr);
            ldm_x4(&bL[2 * p][0], addr + TILE_SZ);
        }

        #pragma unroll
        for (int mi = 0; mi < 2; mi++)
            #pragma unroll
            for (int ni = 0; ni < 8; ni++) {
                mma_bf16(acc[mi][ni], aH[mi], bH[ni]);
                mma_bf16(acc[mi][ni], aH[mi], bL[ni]);
                mma_bf16(acc[mi][ni], aL[mi], bH[ni]);
            }
        __syncthreads();
    }
}

// ---- QKV projection with fused bias + scale + RoPE + split + head layout ----
__global__ __launch_bounds__(256, 1) void mm_qkv(const float* __restrict__ bq,
                                                 const float* __restrict__ bk,
                                                 const float* __restrict__ bv) {
    __shared__ __align__(16) char sm[2 * STG_SZ];
    const int z = blockIdx.z;
    const __nv_bfloat16* Wh = g_wh + (size_t)z * EMB * EMB;
    const __nv_bfloat16* Wl = g_wl + (size_t)z * EMB * EMB;
    const float* bias = (z == 0) ? bq : (z == 1) ? bk : bv;
    const float scale = (z == 0) ? 0.125f : 1.0f;   // hd^-0.5
    __nv_bfloat16* Hd = (z == 0) ? g_qsh : (z == 1) ? g_ksh : g_vsh;
    __nv_bfloat16* Ld = (z == 0) ? g_qsl : (z == 1) ? g_ksl : g_vsl;
    const bool rope = (z < 2);

    const int m0 = blockIdx.y * 128, n0 = blockIdx.x * 128;
    float acc[2][8][4];
    mm_core(g_xh, g_xl, Wh, Wl, m0, n0, sm, acc);

    const int lane = threadIdx.x & 31;
    const int wid  = threadIdx.x >> 5;
    const int wm = wid >> 1, wn = wid & 1;
    const int hh = (n0 + wn * 64) >> 6;          // head index (64-aligned block)
    const int dbase = (lane & 3) * 2;

    #pragma unroll
    for (int mi = 0; mi < 2; mi++) {
        #pragma unroll
        for (int half = 0; half < 2; half++) {
            const int row = m0 + wm * 32 + mi * 16 + (lane >> 2) + half * 8;
            const int s = row >> 1, bb = row & 1;
            float xv[8][2];
            #pragma unroll
            for (int ni = 0; ni < 8; ni++) {
                const int c = n0 + wn * 64 + ni * 8 + dbase;
                xv[ni][0] = (acc[mi][ni][half * 2 + 0] + bias[c])     * scale;
                xv[ni][1] = (acc[mi][ni][half * 2 + 1] + bias[c + 1]) * scale;
            }
            if (rope) {
                #pragma unroll
                for (int t = 0; t < 4; t++) {
                    const int i0 = t * 8 + dbase;
                    const float2 cs0 = g_rope[s * 32 + i0];
                    const float2 cs1 = g_rope[s * 32 + i0 + 1];
                    const float lo0 = xv[t][0],     lo1 = xv[t][1];
                    const float hi0 = xv[t + 4][0], hi1 = xv[t + 4][1];
                    xv[t][0]     = lo0 * cs0.x - hi0 * cs0.y;
                    xv[t][1]     = lo1 * cs1.x - hi1 * cs1.y;
                    xv[t + 4][0] = hi0 * cs0.x + lo0 * cs0.y;
                    xv[t + 4][1] = hi1 * cs1.x + lo1 * cs1.y;
                }
            }
            const size_t base = ((size_t)(bb * NH + hh) * SEQ + s) * HD;
            #pragma unroll
            for (int ni = 0; ni < 8; ni++) {
                const size_t off = base + ni * 8 + dbase;
                __nv_bfloat162 h = __floats2bfloat162_rn(xv[ni][0], xv[ni][1]);
                __nv_bfloat162 l = __floats2bfloat162_rn(
                    xv[ni][0] - __bfloat162float(h.x),
                    xv[ni][1] - __bfloat162float(h.y));
                *(__nv_bfloat162*)(Hd + off) = h;
                *(__nv_bfloat162*)(Ld + off) = l;
            }
        }
    }
}

// ---- output projection: plain fp32 epilogue -------------------------------
__global__ __launch_bounds__(256, 1) void mm_out(const float* __restrict__ bo,
                                                 float* __restrict__ out) {
    __shared__ __align__(16) char sm[2 * STG_SZ];
    const int m0 = blockIdx.y * 128, n0 = blockIdx.x * 128;
    float acc[2][8][4];
    mm_core(g_ah, g_al, g_wh + (size_t)3 * EMB * EMB,
            g_wl + (size_t)3 * EMB * EMB, m0, n0, sm, acc);

    const int lane = threadIdx.x & 31;
    const int wid  = threadIdx.x >> 5;
    const int wm = wid >> 1, wn = wid & 1;
    #pragma unroll
    for (int mi = 0; mi < 2; mi++) {
        #pragma unroll
        for (int ni = 0; ni < 8; ni++) {
            const int r = m0 + wm * 32 + mi * 16 + (lane >> 2);
            const int c = n0 + wn * 64 + ni * 8 + (lane & 3) * 2;
            float2 v0, v1;
            v0.x = acc[mi][ni][0] + bo[c];
            v0.y = acc[mi][ni][1] + bo[c + 1];
            v1.x = acc[mi][ni][2] + bo[c];
            v1.y = acc[mi][ni][3] + bo[c + 1];
            *(float2*)(out + (size_t)r * EMB + c)       = v0;
            *(float2*)(out + (size_t)(r + 8) * EMB + c) = v1;
        }
    }
}

// ================= tensor-core flash attention (split bf16) =================
#define ABKV   64
#define A_RS   144
#define A_KT   (64 * A_RS)
#define A_STG  (4 * A_KT)
#define A_SMEM (2 * A_STG)
#define A_NT   (SEQ / ABKV)

__device__ __forceinline__ void kv_load(uint32_t stb, int g, int kv0, int tid) {
    #pragma unroll
    for (int i = 0; i < 8; i++) {
        const int gid  = i * 256 + tid;
        const int tile = gid >> 9;
        const int gi   = gid & 511;
        const int row  = gi >> 3, ch = gi & 7;
        const __nv_bfloat16* base =
            (tile == 0) ? g_ksh : (tile == 1) ? g_ksl : (tile == 2) ? g_vsh : g_vsl;
        const void* src = base + ((size_t)g * SEQ + kv0 + row) * HD + ch * 8;
        cp_async16(stb + tile * A_KT + row * A_RS + ch * 16, src);
    }
}

__global__ __launch_bounds__(256, 1) void attn_mma() {
    extern __shared__ __align__(16) char dynsm[];
    const uint32_t smb = smem_to_u32(dynsm);
    const int g  = blockIdx.y;
    const int qb = blockIdx.x;
    const int tid = threadIdx.x, lane = tid & 31, wid = tid >> 5;

    // ---- stage Q (hi then lo) through smem -> register fragments ----
    uint32_t qhf[4][4], qlf[4][4];
    {
        const __nv_bfloat16* qsrc[2] = { g_qsh, g_qsl };
        for (int pass = 0; pass < 2; pass++) {
            #pragma unroll
            for (int i = 0; i < 4; i++) {
                const int gid = i * 256 + tid;
                const int row = gid >> 3, ch = gid & 7;
                *(uint4*)(dynsm + row * A_RS + ch * 16) =
                    *(const uint4*)(qsrc[pass] + ((size_t)g * SEQ + qb * 128 + row) * HD + ch * 8);
            }
            __syncthreads();
            #pragma unroll
            for (int kt = 0; kt < 4; kt++) {
                const uint32_t addr = smb + (wid * 16 + (lane & 15)) * A_RS
                                    + kt * 32 + (lane >> 4) * 16;
                ldm_x4(pass ? qlf[kt] : qhf[kt], addr);
            }
            __syncthreads();
        }
    }

    float O[8][4];
    #pragma unroll
    for (int nd = 0; nd < 8; nd++)
        #pragma unroll
        for (int j = 0; j < 4; j++) O[nd][j] = 0.f;
    float m_lo = -1e30f, m_hi = -1e30f, l_lo = 0.f, l_hi = 0.f;

    kv_load(smb, g, 0, tid);
    cp_commit();

    for (int t = 0; t < A_NT; t++) {
        __syncthreads();
        if (t + 1 < A_NT) {
            kv_load(smb + ((t + 1) & 1) * A_STG, g, (t + 1) * ABKV, tid);
            cp_commit();
            cp_wait<1>();
        } else {
            cp_wait<0>();
        }
        __syncthreads();
        const uint32_t stb = smb + (t & 1) * A_STG;

        // ---- S = Q K^T (3-way split); K frags via ldmatrix.x4 (2 n-tiles) ----
        float S[8][4];
        #pragma unroll
        for (int nt = 0; nt < 8; nt++)
            #pragma unroll
            for (int j = 0; j < 4; j++) S[nt][j] = 0.f;
        #pragma unroll
        for (int kt = 0; kt < 4; kt++) {
            #pragma unroll
            for (int p = 0; p < 4; p++) {
                uint32_t bh[4], bl[4];
                const uint32_t row = p * 16 + (lane & 7) + ((lane >> 4) << 3);
                const uint32_t addr = stb + row * A_RS + kt * 32 + ((lane >> 3) & 1) * 16;
                ldm_x4(bh, addr);
                ldm_x4(bl, addr + A_KT);
                mma_bf16(S[2 * p],     qhf[kt], &bh[0]);
                mma_bf16(S[2 * p],     qhf[kt], &bl[0]);
                mma_bf16(S[2 * p],     qlf[kt], &bh[0]);
                mma_bf16(S[2 * p + 1], qhf[kt], &bh[2]);
                mma_bf16(S[2 * p + 1], qhf[kt], &bl[2]);
                mma_bf16(S[2 * p + 1], qlf[kt], &bh[2]);
            }
        }

        // ---- online softmax ----
        float tm_lo = -1e30f, tm_hi = -1e30f;
        #pragma unroll
        for (int nt = 0; nt < 8; nt++) {
            tm_lo = fmaxf(tm_lo, fmaxf(S[nt][0], S[nt][1]));
            tm_hi = fmaxf(tm_hi, fmaxf(S[nt][2], S[nt][3]));
        }
        tm_lo = fmaxf(tm_lo, __shfl_xor_sync(0xffffffffu, tm_lo, 1));
        tm_lo = fmaxf(tm_lo, __shfl_xor_sync(0xffffffffu, tm_lo, 2));
        tm_hi = fmaxf(tm_hi, __shfl_xor_sync(0xffffffffu, tm_hi, 1));
        tm_hi = fmaxf(tm_hi, __shfl_xor_sync(0xffffffffu, tm_hi, 2));

        const float mn_lo = fmaxf(m_lo, tm_lo);
        const float mn_hi = fmaxf(m_hi, tm_hi);
        const float corr_lo = ex2((m_lo - mn_lo) * L2E);
        const float corr_hi = ex2((m_hi - mn_hi) * L2E);
        m_lo = mn_lo; m_hi = mn_hi;
        l_lo *= corr_lo; l_hi *= corr_hi;
        #pragma unroll
        for (int nd = 0; nd < 8; nd++) {
            O[nd][0] *= corr_lo; O[nd][1] *= corr_lo;
            O[nd][2] *= corr_hi; O[nd][3] *= corr_hi;
        }
        const float mb_lo = mn_lo * L2E, mb_hi = mn_hi * L2E;

        uint32_t aPh[4][4], aPl[4][4];
        #pragma unroll
        for (int kt = 0; kt < 4; kt++) {
            #pragma unroll
            for (int half = 0; half < 2; half++) {
                const int nt = 2 * kt + half;
                const float p0 = ex2(fmaf(S[nt][0], L2E, -mb_lo));
                const float p1 = ex2(fmaf(S[nt][1], L2E, -mb_lo));
                const float p2 = ex2(fmaf(S[nt][2], L2E, -mb_hi));
                const float p3 = ex2(fmaf(S[nt][3], L2E, -mb_hi));
                l_lo += p0 + p1; l_hi += p2 + p3;
                __nv_bfloat162 h01 = __floats2bfloat162_rn(p0, p1);
                __nv_bfloat162 h23 = __floats2bfloat162_rn(p2, p3);
                aPh[kt][half * 2 + 0] = b2u(h01);
                aPh[kt][half * 2 + 1] = b2u(h23);
                __nv_bfloat162 l01 = __floats2bfloat162_rn(
                    p0 - __bfloat162float(h01.x), p1 - __bfloat162float(h01.y));
                __nv_bfloat162 l23 = __floats2bfloat162_rn(
                    p2 - __bfloat162float(h23.x), p3 - __bfloat162float(h23.y));
                aPl[kt][half * 2 + 0] = b2u(l01);
                aPl[kt][half * 2 + 1] = b2u(l23);
            }
        }

        // ---- O += P V (3-way split) ----
        #pragma unroll
        for (int kt = 0; kt < 4; kt++) {
            #pragma unroll
            for (int ndp = 0; ndp < 4; ndp++) {
                uint32_t vh[4], vl[4];
                const uint32_t addr = stb + 2 * A_KT
                                    + (kt * 16 + (lane & 15)) * A_RS
                                    + ndp * 32 + (lane >> 4) * 16;
                ldm_x4_t(vh, addr);
                ldm_x4_t(vl, addr + A_KT);
                mma_bf16(O[2 * ndp],     aPh[kt], &vh[0]);
                mma_bf16(O[2 * ndp],     aPh[kt], &vl[0]);
                mma_bf16(O[2 * ndp],     aPl[kt], &vh[0]);
                mma_bf16(O[2 * ndp + 1], aPh[kt], &vh[2]);
                mma_bf16(O[2 * ndp + 1], aPh[kt], &vl[2]);
                mma_bf16(O[2 * ndp + 1], aPl[kt], &vh[2]);
            }
        }
    }

    // ---- finalize ----
    l_lo += __shfl_xor_sync(0xffffffffu, l_lo, 1);
    l_lo += __shfl_xor_sync(0xffffffffu, l_lo, 2);
    l_hi += __shfl_xor_sync(0xffffffffu, l_hi, 1);
    l_hi += __shfl_xor_sync(0xffffffffu, l_hi, 2);
    const float il_lo = 1.f / l_lo, il_hi = 1.f / l_hi;

    const int b  = g >> 4;
    const int hh = g & 15;
    const int r0 = qb * 128 + wid * 16 + (lane >> 2);
    #pragma unroll
    for (int nd = 0; nd < 8; nd++) {
        const int col = hh * HD + nd * 8 + (lane & 3) * 2;
        {
            const float v0 = O[nd][0] * il_lo, v1 = O[nd][1] * il_lo;
            __nv_bfloat162 h = __floats2bfloat162_rn(v0, v1);
            __nv_bfloat162 l = __floats2bfloat162_rn(v0 - __bfloat162float(h.x),
                                                     v1 - __bfloat162float(h.y));
            const size_t off = (size_t)(r0 * BATCH + b) * EMB + col;
            *(__nv_bfloat162*)(g_ah + off) = h;
            *(__nv_bfloat162*)(g_al + off) = l;
        }
        {
            const float v0 = O[nd][2] * il_hi, v1 = O[nd][3] * il_hi;
            __nv_bfloat162 h = __floats2bfloat162_rn(v0, v1);
            __nv_bfloat162 l = __floats2bfloat162_rn(v0 - __bfloat162float(h.x),
                                                     v1 - __bfloat162float(h.y));
            const size_t off = (size_t)((r0 + 8) * BATCH + b) * EMB + col;
            *(__nv_bfloat162*)(g_ah + off) = h;
            *(__nv_bfloat162*)(g_al + off) = l;
        }
    }
}

// ---------------- launch ----------------------------------------------------
extern "C" void kernel_launch(void* const* d_in, const int* in_sizes, int n_in,
                              void* d_out, int out_size) {
    (void)in_sizes; (void)n_in; (void)out_size;
    const float* query = (const float*)d_in[0];
    const float* bq    = (const float*)d_in[2];
    const float* bk    = (const float*)d_in[4];
    const float* bv    = (const float*)d_in[6];
    const float* bo    = (const float*)d_in[8];
    float* out = (float*)d_out;

    cudaFuncSetAttribute(attn_mma, cudaFuncAttributeMaxDynamicSharedMemorySize, A_SMEM);

    __nv_bfloat16* xh; __nv_bfloat16* xl;
    cudaGetSymbolAddress((void**)&xh, g_xh);
    cudaGetSymbolAddress((void**)&xl, g_xl);

    // 0) fp32 -> bf16 hi/lo splits (X and weights) + rope table
    cvt_split<<<MROWS * EMB / 1024, 256>>>(query, xh, xl);
    dim3 gw(EMB * EMB / 1024, 1, 4);
    cvt_w<<<gw, 256>>>((const float*)d_in[1], (const float*)d_in[3],
                       (const float*)d_in[5], (const float*)d_in[7]);
    rope_table<<<SEQ * 32 / 256, 256>>>();

    // 1) fused QKV projection + bias + scale + RoPE + split + head layout
    dim3 gq(EMB / 128, MROWS / 128, 3);
    mm_qkv<<<gq, 256>>>(bq, bk, bv);

    // 2) tensor-core flash attention (writes g_ah/g_al directly)
    dim3 ga(SEQ / 128, NHEADS);
    attn_mma<<<ga, 256, A_SMEM>>>();

    // 3) output projection
    dim3 go(EMB / 128, MROWS / 128);
    mm_out<<<go, 256>>>(bo, out);
}

// round 7
// speedup vs baseline: 3.6684x; 1.1302x over previous
#include <cuda_runtime.h>
#include <cuda_bf16.h>
#include <cstdint>
#include <math.h>

// Problem constants (fixed shapes)
#define SEQ    2048
#define BATCH  2
#define EMB    1024
#define NH     16
#define HD     64
#define NHEADS (BATCH * NH)     // 32 flattened heads
#define MROWS  (SEQ * BATCH)    // 4096 token rows
#define L2E    1.4426950408889634f

// ---------------- scratch (static device memory; no allocs) ----------------
// split bf16 head-layout tensors [g][s][d]
__device__ __nv_bfloat16 g_qsh[NHEADS * SEQ * HD];
__device__ __nv_bfloat16 g_qsl[NHEADS * SEQ * HD];
__device__ __nv_bfloat16 g_ksh[NHEADS * SEQ * HD];
__device__ __nv_bfloat16 g_ksl[NHEADS * SEQ * HD];
__device__ __nv_bfloat16 g_vsh[NHEADS * SEQ * HD];
__device__ __nv_bfloat16 g_vsl[NHEADS * SEQ * HD];

// bf16 hi/lo split GEMM operands
__device__ __nv_bfloat16 g_xh[MROWS * EMB];
__device__ __nv_bfloat16 g_xl[MROWS * EMB];
__device__ __nv_bfloat16 g_wh[4 * EMB * EMB];   // Wq, Wk, Wv, Wo
__device__ __nv_bfloat16 g_wl[4 * EMB * EMB];
__device__ __nv_bfloat16 g_ah[MROWS * EMB];     // attention out (split)
__device__ __nv_bfloat16 g_al[MROWS * EMB];

// rope cos/sin table: [s][i] i in [0,32), .x = cos, .y = sin
__device__ float2 g_rope[SEQ * 32];

// ======================= helpers ===========================================
__device__ __forceinline__ uint32_t smem_to_u32(const void* smem_ptr) {
    uint32_t addr;
    asm("{ .reg .u64 tmp; cvta.to.shared.u64 tmp, %1; cvt.u32.u64 %0, tmp; }"
        : "=r"(addr) : "l"(smem_ptr));
    return addr;
}
__device__ __forceinline__ void ldm_x4(uint32_t* r, uint32_t addr) {
    asm volatile("ldmatrix.sync.aligned.m8n8.x4.shared.b16 {%0,%1,%2,%3}, [%4];"
                 : "=r"(r[0]), "=r"(r[1]), "=r"(r[2]), "=r"(r[3]) : "r"(addr));
}
__device__ __forceinline__ void ldm_x4_t(uint32_t* r, uint32_t addr) {
    asm volatile("ldmatrix.sync.aligned.m8n8.x4.trans.shared.b16 {%0,%1,%2,%3}, [%4];"
                 : "=r"(r[0]), "=r"(r[1]), "=r"(r[2]), "=r"(r[3]) : "r"(addr));
}
__device__ __forceinline__ void mma_bf16(float* d, const uint32_t* a, const uint32_t* b) {
    asm volatile(
        "mma.sync.aligned.m16n8k16.row.col.f32.bf16.bf16.f32 "
        "{%0,%1,%2,%3}, {%4,%5,%6,%7}, {%8,%9}, {%0,%1,%2,%3};"
        : "+f"(d[0]), "+f"(d[1]), "+f"(d[2]), "+f"(d[3])
        : "r"(a[0]), "r"(a[1]), "r"(a[2]), "r"(a[3]), "r"(b[0]), "r"(b[1]));
}
__device__ __forceinline__ void cp_async16(uint32_t dst, const void* src) {
    asm volatile("cp.async.ca.shared.global [%0], [%1], 16;" :: "r"(dst), "l"(src));
}
__device__ __forceinline__ void cp_commit() {
    asm volatile("cp.async.commit_group;" ::: "memory");
}
template <int N>
__device__ __forceinline__ void cp_wait() {
    asm volatile("cp.async.wait_group %0;" :: "n"(N) : "memory");
}
__device__ __forceinline__ float ex2(float x) {
    float r; asm("ex2.approx.f32 %0, %1;" : "=f"(r) : "f"(x)); return r;
}
__device__ __forceinline__ uint32_t b2u(__nv_bfloat162 h) {
    return *reinterpret_cast<uint32_t*>(&h);
}

// ======================= fp32 -> bf16 hi/lo conversion ======================
__device__ __forceinline__ void split4(const float4 x, __nv_bfloat162* hi2,
                                       __nv_bfloat162* lo2, size_t i2) {
    __nv_bfloat16 h0 = __float2bfloat16(x.x);
    __nv_bfloat16 h1 = __float2bfloat16(x.y);
    __nv_bfloat16 h2 = __float2bfloat16(x.z);
    __nv_bfloat16 h3 = __float2bfloat16(x.w);
    hi2[i2]     = __nv_bfloat162(h0, h1);
    hi2[i2 + 1] = __nv_bfloat162(h2, h3);
    lo2[i2]     = __nv_bfloat162(__float2bfloat16(x.x - __bfloat162float(h0)),
                                 __float2bfloat16(x.y - __bfloat162float(h1)));
    lo2[i2 + 1] = __nv_bfloat162(__float2bfloat16(x.z - __bfloat162float(h2)),
                                 __float2bfloat16(x.w - __bfloat162float(h3)));
}

__global__ __launch_bounds__(256) void cvt_split(const float* __restrict__ src,
                                                 __nv_bfloat16* __restrict__ hi,
                                                 __nv_bfloat16* __restrict__ lo) {
    const size_t i4 = (size_t)blockIdx.x * 256 + threadIdx.x;
    float4 x = ((const float4*)src)[i4];
    split4(x, (__nv_bfloat162*)hi, (__nv_bfloat162*)lo, i4 * 2);
}

__global__ __launch_bounds__(256) void cvt_w(const float* __restrict__ Wq,
                                             const float* __restrict__ Wk,
                                             const float* __restrict__ Wv,
                                             const float* __restrict__ Wo) {
    const int z = blockIdx.z;
    const float* src = (z == 0) ? Wq : (z == 1) ? Wk : (z == 2) ? Wv : Wo;
    const size_t base4 = (size_t)z * (EMB * EMB / 4);
    const size_t i4 = base4 + (size_t)blockIdx.x * 256 + threadIdx.x;
    float4 x = ((const float4*)src)[(size_t)blockIdx.x * 256 + threadIdx.x];
    split4(x, (__nv_bfloat162*)g_wh, (__nv_bfloat162*)g_wl, i4 * 2);
}

// rope table: cos/sin(s * 10000^(-i/32)) for i in [0,32)
__global__ __launch_bounds__(256) void rope_table() {
    const int idx = blockIdx.x * 256 + threadIdx.x;   // SEQ*32 entries
    const int s = idx >> 5, i = idx & 31;
    const float inv_f = exp2f(-(float)i * (13.287712379549449f / 32.f));
    float sn, c;
    sincosf((float)s * inv_f, &sn, &c);
    g_rope[idx] = make_float2(c, sn);
}

// ======================= mma.sync split-bf16 GEMM core ======================
// CTA 128x128, BK=32, 512 threads (16 warps, warp tile 16x64),
// 3-stage cp.async pipeline, stride-80 rows (conflict-free for ldmatrix).
#define MM_BK   32
#define MM_RS   80                       // bytes per 32-bf16 row (64 + 16 pad)
#define MM_TS   (128 * MM_RS)            // 10240 per tile
#define MM_STG  (4 * MM_TS)              // Ah, Al, Wh, Wl = 40960
#define MM_SMEM (3 * MM_STG)             // 122880
#define MM_NIT  (EMB / MM_BK)            // 32

__device__ __forceinline__ void mm_stage_load(uint32_t stb,
                                              const __nv_bfloat16* pAh,
                                              const __nv_bfloat16* pAl,
                                              const __nv_bfloat16* pWh,
                                              const __nv_bfloat16* pWl,
                                              int k0, int tid) {
    const int row = tid >> 2, ch = tid & 3;
    const uint32_t off = (uint32_t)(row * MM_RS + ch * 16);
    const size_t goff = (size_t)row * EMB + k0 + ch * 8;
    cp_async16(stb + 0 * MM_TS + off, pAh + goff);
    cp_async16(stb + 1 * MM_TS + off, pAl + goff);
    cp_async16(stb + 2 * MM_TS + off, pWh + goff);
    cp_async16(stb + 3 * MM_TS + off, pWl + goff);
}

// mainloop: fills acc[8][4] for this thread's 16x64 warp tile at (m0, n0).
__device__ __forceinline__ void mm_core(const __nv_bfloat16* __restrict__ Ah,
                                        const __nv_bfloat16* __restrict__ Al,
                                        const __nv_bfloat16* __restrict__ Wh,
                                        const __nv_bfloat16* __restrict__ Wl,
                                        int m0, int n0, char* sm,
                                        float acc[8][4])
{
    const uint32_t smb = smem_to_u32(sm);
    const int tid  = threadIdx.x;
    const int lane = tid & 31;
    const int wid  = tid >> 5;
    const int wm   = wid >> 1;           // 0..7 : 16-row band
    const int wn   = wid & 1;            // 0..1 : 64-col band

    const __nv_bfloat16* pAh = Ah + (size_t)m0 * EMB;
    const __nv_bfloat16* pAl = Al + (size_t)m0 * EMB;
    const __nv_bfloat16* pWh = Wh + (size_t)n0 * EMB;
    const __nv_bfloat16* pWl = Wl + (size_t)n0 * EMB;

    #pragma unroll
    for (int ni = 0; ni < 8; ni++)
        #pragma unroll
        for (int j = 0; j < 4; j++) acc[ni][j] = 0.f;

    // prologue: stages 0, 1
    mm_stage_load(smb + 0 * MM_STG, pAh, pAl, pWh, pWl, 0, tid);
    cp_commit();
    mm_stage_load(smb + 1 * MM_STG, pAh, pAl, pWh, pWl, MM_BK, tid);
    cp_commit();

    int cs = 0;                          // compute stage
    int ls = 2;                          // load stage for chunk k+2
    for (int k = 0; k < MM_NIT; k++) {
        cp_wait<1>();
        __syncthreads();
        const uint32_t tb = smb + cs * MM_STG;

        #pragma unroll
        for (int kk = 0; kk < 2; kk++) {
            uint32_t aH[4], aL[4];
            const uint32_t aaddr = tb + (wm * 16 + (lane & 15)) * MM_RS
                                 + kk * 32 + (lane >> 4) * 16;
            ldm_x4(aH, aaddr);
            ldm_x4(aL, aaddr + MM_TS);
            uint32_t bH[8][2], bL[8][2];
            #pragma unroll
            for (int p = 0; p < 4; p++) {
                const uint32_t row = wn * 64 + p * 16 + (lane & 7) + ((lane >> 4) << 3);
                const uint32_t baddr = tb + 2 * MM_TS + row * MM_RS
                                     + kk * 32 + ((lane >> 3) & 1) * 16;
                ldm_x4(&bH[2 * p][0], baddr);
                ldm_x4(&bL[2 * p][0], baddr + MM_TS);
            }
            #pragma unroll
            for (int ni = 0; ni < 8; ni++) {
                mma_bf16(acc[ni], aH, bH[ni]);
                mma_bf16(acc[ni], aH, bL[ni]);
                mma_bf16(acc[ni], aL, bH[ni]);
            }
        }

        if (k + 2 < MM_NIT)
            mm_stage_load(smb + ls * MM_STG, pAh, pAl, pWh, pWl, (k + 2) * MM_BK, tid);
        cp_commit();                     // always commit (empty groups keep count exact)
        cs = (cs == 2) ? 0 : cs + 1;
        ls = (ls == 2) ? 0 : ls + 1;
    }
}

// ---- QKV projection with fused bias + scale + RoPE + split + head layout ----
__global__ __launch_bounds__(512, 1) void mm_qkv(const float* __restrict__ bq,
                                                 const float* __restrict__ bk,
                                                 const float* __restrict__ bv) {
    extern __shared__ __align__(16) char mmsm[];
    const int z = blockIdx.z;
    const __nv_bfloat16* Wh = g_wh + (size_t)z * EMB * EMB;
    const __nv_bfloat16* Wl = g_wl + (size_t)z * EMB * EMB;
    const float* bias = (z == 0) ? bq : (z == 1) ? bk : bv;
    const float scale = (z == 0) ? 0.125f : 1.0f;   // hd^-0.5
    __nv_bfloat16* Hd = (z == 0) ? g_qsh : (z == 1) ? g_ksh : g_vsh;
    __nv_bfloat16* Ld = (z == 0) ? g_qsl : (z == 1) ? g_ksl : g_vsl;
    const bool rope = (z < 2);

    const int m0 = blockIdx.y * 128, n0 = blockIdx.x * 128;
    float acc[8][4];
    mm_core(g_xh, g_xl, Wh, Wl, m0, n0, mmsm, acc);

    const int lane = threadIdx.x & 31;
    const int wid  = threadIdx.x >> 5;
    const int wm = wid >> 1, wn = wid & 1;
    const int hh = (n0 + wn * 64) >> 6;          // head index (64-aligned block)
    const int dbase = (lane & 3) * 2;

    #pragma unroll
    for (int half = 0; half < 2; half++) {
        const int row = m0 + wm * 16 + (lane >> 2) + half * 8;
        const int s = row >> 1, bb = row & 1;
        float xv[8][2];
        #pragma unroll
        for (int ni = 0; ni < 8; ni++) {
            const int c = n0 + wn * 64 + ni * 8 + dbase;
            xv[ni][0] = (acc[ni][half * 2 + 0] + bias[c])     * scale;
            xv[ni][1] = (acc[ni][half * 2 + 1] + bias[c + 1]) * scale;
        }
        if (rope) {
            #pragma unroll
            for (int t = 0; t < 4; t++) {
                const int i0 = t * 8 + dbase;
                const float2 cs0 = g_rope[s * 32 + i0];
                const float2 cs1 = g_rope[s * 32 + i0 + 1];
                const float lo0 = xv[t][0],     lo1 = xv[t][1];
                const float hi0 = xv[t + 4][0], hi1 = xv[t + 4][1];
                xv[t][0]     = lo0 * cs0.x - hi0 * cs0.y;
                xv[t][1]     = lo1 * cs1.x - hi1 * cs1.y;
                xv[t + 4][0] = hi0 * cs0.x + lo0 * cs0.y;
                xv[t + 4][1] = hi1 * cs1.x + lo1 * cs1.y;
            }
        }
        const size_t base = ((size_t)(bb * NH + hh) * SEQ + s) * HD;
        #pragma unroll
        for (int ni = 0; ni < 8; ni++) {
            const size_t off = base + ni * 8 + dbase;
            __nv_bfloat162 h = __floats2bfloat162_rn(xv[ni][0], xv[ni][1]);
            __nv_bfloat162 l = __floats2bfloat162_rn(
                xv[ni][0] - __bfloat162float(h.x),
                xv[ni][1] - __bfloat162float(h.y));
            *(__nv_bfloat162*)(Hd + off) = h;
            *(__nv_bfloat162*)(Ld + off) = l;
        }
    }
}

// ---- output projection: plain fp32 epilogue -------------------------------
__global__ __launch_bounds__(512, 1) void mm_out(const float* __restrict__ bo,
                                                 float* __restrict__ out) {
    extern __shared__ __align__(16) char mmsm[];
    const int m0 = blockIdx.y * 128, n0 = blockIdx.x * 128;
    float acc[8][4];
    mm_core(g_ah, g_al, g_wh + (size_t)3 * EMB * EMB,
            g_wl + (size_t)3 * EMB * EMB, m0, n0, mmsm, acc);

    const int lane = threadIdx.x & 31;
    const int wid  = threadIdx.x >> 5;
    const int wm = wid >> 1, wn = wid & 1;
    #pragma unroll
    for (int ni = 0; ni < 8; ni++) {
        const int r = m0 + wm * 16 + (lane >> 2);
        const int c = n0 + wn * 64 + ni * 8 + (lane & 3) * 2;
        float2 v0, v1;
        v0.x = acc[ni][0] + bo[c];
        v0.y = acc[ni][1] + bo[c + 1];
        v1.x = acc[ni][2] + bo[c];
        v1.y = acc[ni][3] + bo[c + 1];
        *(float2*)(out + (size_t)r * EMB + c)       = v0;
        *(float2*)(out + (size_t)(r + 8) * EMB + c) = v1;
    }
}

// ================= tensor-core flash attention (split bf16) =================
#define ABKV   64
#define A_RS   144
#define A_KT   (64 * A_RS)
#define A_STG  (4 * A_KT)
#define A_SMEM (2 * A_STG)
#define A_NT   (SEQ / ABKV)

__device__ __forceinline__ void kv_load(uint32_t stb, int g, int kv0, int tid) {
    #pragma unroll
    for (int i = 0; i < 8; i++) {
        const int gid  = i * 256 + tid;
        const int tile = gid >> 9;
        const int gi   = gid & 511;
        const int row  = gi >> 3, ch = gi & 7;
        const __nv_bfloat16* base =
            (tile == 0) ? g_ksh : (tile == 1) ? g_ksl : (tile == 2) ? g_vsh : g_vsl;
        const void* src = base + ((size_t)g * SEQ + kv0 + row) * HD + ch * 8;
        cp_async16(stb + tile * A_KT + row * A_RS + ch * 16, src);
    }
}

__global__ __launch_bounds__(256, 1) void attn_mma() {
    extern __shared__ __align__(16) char dynsm[];
    const uint32_t smb = smem_to_u32(dynsm);
    const int g  = blockIdx.y;
    const int qb = blockIdx.x;
    const int tid = threadIdx.x, lane = tid & 31, wid = tid >> 5;

    // ---- stage Q (hi then lo) through smem -> register fragments ----
    uint32_t qhf[4][4], qlf[4][4];
    {
        const __nv_bfloat16* qsrc[2] = { g_qsh, g_qsl };
        for (int pass = 0; pass < 2; pass++) {
            #pragma unroll
            for (int i = 0; i < 4; i++) {
                const int gid = i * 256 + tid;
                const int row = gid >> 3, ch = gid & 7;
                *(uint4*)(dynsm + row * A_RS + ch * 16) =
                    *(const uint4*)(qsrc[pass] + ((size_t)g * SEQ + qb * 128 + row) * HD + ch * 8);
            }
            __syncthreads();
            #pragma unroll
            for (int kt = 0; kt < 4; kt++) {
                const uint32_t addr = smb + (wid * 16 + (lane & 15)) * A_RS
                                    + kt * 32 + (lane >> 4) * 16;
                ldm_x4(pass ? qlf[kt] : qhf[kt], addr);
            }
            __syncthreads();
        }
    }

    float O[8][4];
    #pragma unroll
    for (int nd = 0; nd < 8; nd++)
        #pragma unroll
        for (int j = 0; j < 4; j++) O[nd][j] = 0.f;
    float m_lo = -1e30f, m_hi = -1e30f, l_lo = 0.f, l_hi = 0.f;

    kv_load(smb, g, 0, tid);
    cp_commit();

    for (int t = 0; t < A_NT; t++) {
        __syncthreads();
        if (t + 1 < A_NT) {
            kv_load(smb + ((t + 1) & 1) * A_STG, g, (t + 1) * ABKV, tid);
            cp_commit();
            cp_wait<1>();
        } else {
            cp_wait<0>();
        }
        __syncthreads();
        const uint32_t stb = smb + (t & 1) * A_STG;

        // ---- S = Q K^T (3-way split); K frags via ldmatrix.x4 (2 n-tiles) ----
        float S[8][4];
        #pragma unroll
        for (int nt = 0; nt < 8; nt++)
            #pragma unroll
            for (int j = 0; j < 4; j++) S[nt][j] = 0.f;
        #pragma unroll
        for (int kt = 0; kt < 4; kt++) {
            #pragma unroll
            for (int p = 0; p < 4; p++) {
                uint32_t bh[4], bl[4];
                const uint32_t row = p * 16 + (lane & 7) + ((lane >> 4) << 3);
                const uint32_t addr = stb + row * A_RS + kt * 32 + ((lane >> 3) & 1) * 16;
                ldm_x4(bh, addr);
                ldm_x4(bl, addr + A_KT);
                mma_bf16(S[2 * p],     qhf[kt], &bh[0]);
                mma_bf16(S[2 * p],     qhf[kt], &bl[0]);
                mma_bf16(S[2 * p],     qlf[kt], &bh[0]);
                mma_bf16(S[2 * p + 1], qhf[kt], &bh[2]);
                mma_bf16(S[2 * p + 1], qhf[kt], &bl[2]);
                mma_bf16(S[2 * p + 1], qlf[kt], &bh[2]);
            }
        }

        // ---- online softmax ----
        float tm_lo = -1e30f, tm_hi = -1e30f;
        #pragma unroll
        for (int nt = 0; nt < 8; nt++) {
            tm_lo = fmaxf(tm_lo, fmaxf(S[nt][0], S[nt][1]));
            tm_hi = fmaxf(tm_hi, fmaxf(S[nt][2], S[nt][3]));
        }
        tm_lo = fmaxf(tm_lo, __shfl_xor_sync(0xffffffffu, tm_lo, 1));
        tm_lo = fmaxf(tm_lo, __shfl_xor_sync(0xffffffffu, tm_lo, 2));
        tm_hi = fmaxf(tm_hi, __shfl_xor_sync(0xffffffffu, tm_hi, 1));
        tm_hi = fmaxf(tm_hi, __shfl_xor_sync(0xffffffffu, tm_hi, 2));

        const float mn_lo = fmaxf(m_lo, tm_lo);
        const float mn_hi = fmaxf(m_hi, tm_hi);
        const float corr_lo = ex2((m_lo - mn_lo) * L2E);
        const float corr_hi = ex2((m_hi - mn_hi) * L2E);
        m_lo = mn_lo; m_hi = mn_hi;
        l_lo *= corr_lo; l_hi *= corr_hi;
        #pragma unroll
        for (int nd = 0; nd < 8; nd++) {
            O[nd][0] *= corr_lo; O[nd][1] *= corr_lo;
            O[nd][2] *= corr_hi; O[nd][3] *= corr_hi;
        }
        const float mb_lo = mn_lo * L2E, mb_hi = mn_hi * L2E;

        uint32_t aPh[4][4], aPl[4][4];
        #pragma unroll
        for (int kt = 0; kt < 4; kt++) {
            #pragma unroll
            for (int half = 0; half < 2; half++) {
                const int nt = 2 * kt + half;
                const float p0 = ex2(fmaf(S[nt][0], L2E, -mb_lo));
                const float p1 = ex2(fmaf(S[nt][1], L2E, -mb_lo));
                const float p2 = ex2(fmaf(S[nt][2], L2E, -mb_hi));
                const float p3 = ex2(fmaf(S[nt][3], L2E, -mb_hi));
                l_lo += p0 + p1; l_hi += p2 + p3;
                __nv_bfloat162 h01 = __floats2bfloat162_rn(p0, p1);
                __nv_bfloat162 h23 = __floats2bfloat162_rn(p2, p3);
                aPh[kt][half * 2 + 0] = b2u(h01);
                aPh[kt][half * 2 + 1] = b2u(h23);
                __nv_bfloat162 l01 = __floats2bfloat162_rn(
                    p0 - __bfloat162float(h01.x), p1 - __bfloat162float(h01.y));
                __nv_bfloat162 l23 = __floats2bfloat162_rn(
                    p2 - __bfloat162float(h23.x), p3 - __bfloat162float(h23.y));
                aPl[kt][half * 2 + 0] = b2u(l01);
                aPl[kt][half * 2 + 1] = b2u(l23);
            }
        }

        // ---- O += P V (3-way split) ----
        #pragma unroll
        for (int kt = 0; kt < 4; kt++) {
            #pragma unroll
            for (int ndp = 0; ndp < 4; ndp++) {
                uint32_t vh[4], vl[4];
                const uint32_t addr = stb + 2 * A_KT
                                    + (kt * 16 + (lane & 15)) * A_RS
                                    + ndp * 32 + (lane >> 4) * 16;
                ldm_x4_t(vh, addr);
                ldm_x4_t(vl, addr + A_KT);
                mma_bf16(O[2 * ndp],     aPh[kt], &vh[0]);
                mma_bf16(O[2 * ndp],     aPh[kt], &vl[0]);
                mma_bf16(O[2 * ndp],     aPl[kt], &vh[0]);
                mma_bf16(O[2 * ndp + 1], aPh[kt], &vh[2]);
                mma_bf16(O[2 * ndp + 1], aPh[kt], &vl[2]);
                mma_bf16(O[2 * ndp + 1], aPl[kt], &vh[2]);
            }
        }
    }

    // ---- finalize ----
    l_lo += __shfl_xor_sync(0xffffffffu, l_lo, 1);
    l_lo += __shfl_xor_sync(0xffffffffu, l_lo, 2);
    l_hi += __shfl_xor_sync(0xffffffffu, l_hi, 1);
    l_hi += __shfl_xor_sync(0xffffffffu, l_hi, 2);
    const float il_lo = 1.f / l_lo, il_hi = 1.f / l_hi;

    const int b  = g >> 4;
    const int hh = g & 15;
    const int r0 = qb * 128 + wid * 16 + (lane >> 2);
    #pragma unroll
    for (int nd = 0; nd < 8; nd++) {
        const int col = hh * HD + nd * 8 + (lane & 3) * 2;
        {
            const float v0 = O[nd][0] * il_lo, v1 = O[nd][1] * il_lo;
            __nv_bfloat162 h = __floats2bfloat162_rn(v0, v1);
            __nv_bfloat162 l = __floats2bfloat162_rn(v0 - __bfloat162float(h.x),
                                                     v1 - __bfloat162float(h.y));
            const size_t off = (size_t)(r0 * BATCH + b) * EMB + col;
            *(__nv_bfloat162*)(g_ah + off) = h;
            *(__nv_bfloat162*)(g_al + off) = l;
        }
        {
            const float v0 = O[nd][2] * il_hi, v1 = O[nd][3] * il_hi;
            __nv_bfloat162 h = __floats2bfloat162_rn(v0, v1);
            __nv_bfloat162 l = __floats2bfloat162_rn(v0 - __bfloat162float(h.x),
                                                     v1 - __bfloat162float(h.y));
            const size_t off = (size_t)((r0 + 8) * BATCH + b) * EMB + col;
            *(__nv_bfloat162*)(g_ah + off) = h;
            *(__nv_bfloat162*)(g_al + off) = l;
        }
    }
}

// ---------------- launch ----------------------------------------------------
extern "C" void kernel_launch(void* const* d_in, const int* in_sizes, int n_in,
                              void* d_out, int out_size) {
    (void)in_sizes; (void)n_in; (void)out_size;
    const float* query = (const float*)d_in[0];
    const float* bq    = (const float*)d_in[2];
    const float* bk    = (const float*)d_in[4];
    const float* bv    = (const float*)d_in[6];
    const float* bo    = (const float*)d_in[8];
    float* out = (float*)d_out;

    cudaFuncSetAttribute(mm_qkv,   cudaFuncAttributeMaxDynamicSharedMemorySize, MM_SMEM);
    cudaFuncSetAttribute(mm_out,   cudaFuncAttributeMaxDynamicSharedMemorySize, MM_SMEM);
    cudaFuncSetAttribute(attn_mma, cudaFuncAttributeMaxDynamicSharedMemorySize, A_SMEM);

    __nv_bfloat16* xh; __nv_bfloat16* xl;
    cudaGetSymbolAddress((void**)&xh, g_xh);
    cudaGetSymbolAddress((void**)&xl, g_xl);

    // 0) fp32 -> bf16 hi/lo splits (X and weights) + rope table
    cvt_split<<<MROWS * EMB / 1024, 256>>>(query, xh, xl);
    dim3 gw(EMB * EMB / 1024, 1, 4);
    cvt_w<<<gw, 256>>>((const float*)d_in[1], (const float*)d_in[3],
                       (const float*)d_in[5], (const float*)d_in[7]);
    rope_table<<<SEQ * 32 / 256, 256>>>();

    // 1) fused QKV projection + bias + scale + RoPE + split + head layout
    dim3 gq(EMB / 128, MROWS / 128, 3);
    mm_qkv<<<gq, 512, MM_SMEM>>>(bq, bk, bv);

    // 2) tensor-core flash attention (writes g_ah/g_al directly)
    dim3 ga(SEQ / 128, NHEADS);
    attn_mma<<<ga, 256, A_SMEM>>>();

    // 3) output projection
    dim3 go(EMB / 128, MROWS / 128);
    mm_out<<<go, 512, MM_SMEM>>>(bo, out);
}

// round 11
// speedup vs baseline: 4.7599x; 1.2975x over previous
#include <cuda_runtime.h>
#include <cuda_bf16.h>
#include <cuda_fp16.h>
#include <cstdint>
#include <math.h>

// Problem constants (fixed shapes)
#define SEQ    2048
#define BATCH  2
#define EMB    1024
#define NH     16
#define HD     64
#define NHEADS (BATCH * NH)     // 32 flattened heads
#define MROWS  (SEQ * BATCH)    // 4096 token rows
#define L2E    1.4426950408889634f

// ---------------- scratch (static device memory; no allocs) ----------------
// attention operands: Q split fp16 hi/lo; K, V single fp16. layout [g][s][d]
__device__ __half g_qhh[NHEADS * SEQ * HD];
__device__ __half g_qhl[NHEADS * SEQ * HD];
__device__ __half g_kf [NHEADS * SEQ * HD];
__device__ __half g_vf [NHEADS * SEQ * HD];

// bf16 hi/lo split GEMM operands (projections stay 3xBF16)
__device__ __nv_bfloat16 g_xh[MROWS * EMB];
__device__ __nv_bfloat16 g_xl[MROWS * EMB];
__device__ __nv_bfloat16 g_wh[4 * EMB * EMB];   // Wq, Wk, Wv, Wo
__device__ __nv_bfloat16 g_wl[4 * EMB * EMB];
__device__ __nv_bfloat16 g_ah[MROWS * EMB];     // attention out (split bf16)
__device__ __nv_bfloat16 g_al[MROWS * EMB];

// rope cos/sin table: [s][i] i in [0,32), .x = cos, .y = sin
__device__ float2 g_rope[SEQ * 32];

// ======================= helpers ===========================================
__device__ __forceinline__ uint32_t smem_to_u32(const void* smem_ptr) {
    uint32_t addr;
    asm("{ .reg .u64 tmp; cvta.to.shared.u64 tmp, %1; cvt.u32.u64 %0, tmp; }"
        : "=r"(addr) : "l"(smem_ptr));
    return addr;
}
__device__ __forceinline__ void ldm_x4(uint32_t* r, uint32_t addr) {
    asm volatile("ldmatrix.sync.aligned.m8n8.x4.shared.b16 {%0,%1,%2,%3}, [%4];"
                 : "=r"(r[0]), "=r"(r[1]), "=r"(r[2]), "=r"(r[3]) : "r"(addr));
}
__device__ __forceinline__ void ldm_x4_t(uint32_t* r, uint32_t addr) {
    asm volatile("ldmatrix.sync.aligned.m8n8.x4.trans.shared.b16 {%0,%1,%2,%3}, [%4];"
                 : "=r"(r[0]), "=r"(r[1]), "=r"(r[2]), "=r"(r[3]) : "r"(addr));
}
__device__ __forceinline__ void mma_bf16(float* d, const uint32_t* a, const uint32_t* b) {
    asm volatile(
        "mma.sync.aligned.m16n8k16.row.col.f32.bf16.bf16.f32 "
        "{%0,%1,%2,%3}, {%4,%5,%6,%7}, {%8,%9}, {%0,%1,%2,%3};"
        : "+f"(d[0]), "+f"(d[1]), "+f"(d[2]), "+f"(d[3])
        : "r"(a[0]), "r"(a[1]), "r"(a[2]), "r"(a[3]), "r"(b[0]), "r"(b[1]));
}
__device__ __forceinline__ void mma_f16(float* d, const uint32_t* a, const uint32_t* b) {
    asm volatile(
        "mma.sync.aligned.m16n8k16.row.col.f32.f16.f16.f32 "
        "{%0,%1,%2,%3}, {%4,%5,%6,%7}, {%8,%9}, {%0,%1,%2,%3};"
        : "+f"(d[0]), "+f"(d[1]), "+f"(d[2]), "+f"(d[3])
        : "r"(a[0]), "r"(a[1]), "r"(a[2]), "r"(a[3]), "r"(b[0]), "r"(b[1]));
}
__device__ __forceinline__ void cp_async16(uint32_t dst, const void* src) {
    asm volatile("cp.async.ca.shared.global [%0], [%1], 16;" :: "r"(dst), "l"(src));
}
__device__ __forceinline__ void cp_commit() {
    asm volatile("cp.async.commit_group;" ::: "memory");
}
template <int N>
__device__ __forceinline__ void cp_wait() {
    asm volatile("cp.async.wait_group %0;" :: "n"(N) : "memory");
}
__device__ __forceinline__ float ex2(float x) {
    float r; asm("ex2.approx.f32 %0, %1;" : "=f"(r) : "f"(x)); return r;
}
__device__ __forceinline__ uint32_t h2u(__half2 h) {
    return *reinterpret_cast<uint32_t*>(&h);
}

// ======================= fp32 -> bf16 hi/lo conversion ======================
__device__ __forceinline__ void split4(const float4 x, __nv_bfloat162* hi2,
                                       __nv_bfloat162* lo2, size_t i2) {
    __nv_bfloat16 h0 = __float2bfloat16(x.x);
    __nv_bfloat16 h1 = __float2bfloat16(x.y);
    __nv_bfloat16 h2 = __float2bfloat16(x.z);
    __nv_bfloat16 h3 = __float2bfloat16(x.w);
    hi2[i2]     = __nv_bfloat162(h0, h1);
    hi2[i2 + 1] = __nv_bfloat162(h2, h3);
    lo2[i2]     = __nv_bfloat162(__float2bfloat16(x.x - __bfloat162float(h0)),
                                 __float2bfloat16(x.y - __bfloat162float(h1)));
    lo2[i2 + 1] = __nv_bfloat162(__float2bfloat16(x.z - __bfloat162float(h2)),
                                 __float2bfloat16(x.w - __bfloat162float(h3)));
}

__global__ __launch_bounds__(256) void cvt_split(const float* __restrict__ src,
                                                 __nv_bfloat16* __restrict__ hi,
                                                 __nv_bfloat16* __restrict__ lo) {
    const size_t i4 = (size_t)blockIdx.x * 256 + threadIdx.x;
    float4 x = ((const float4*)src)[i4];
    split4(x, (__nv_bfloat162*)hi, (__nv_bfloat162*)lo, i4 * 2);
}

__global__ __launch_bounds__(256) void cvt_w(const float* __restrict__ Wq,
                                             const float* __restrict__ Wk,
                                             const float* __restrict__ Wv,
                                             const float* __restrict__ Wo) {
    const int z = blockIdx.z;
    const float* src = (z == 0) ? Wq : (z == 1) ? Wk : (z == 2) ? Wv : Wo;
    const size_t base4 = (size_t)z * (EMB * EMB / 4);
    const size_t i4 = base4 + (size_t)blockIdx.x * 256 + threadIdx.x;
    float4 x = ((const float4*)src)[(size_t)blockIdx.x * 256 + threadIdx.x];
    split4(x, (__nv_bfloat162*)g_wh, (__nv_bfloat162*)g_wl, i4 * 2);
}

// rope table: cos/sin(s * 10000^(-i/32)) for i in [0,32)
__global__ __launch_bounds__(256) void rope_table() {
    const int idx = blockIdx.x * 256 + threadIdx.x;   // SEQ*32 entries
    const int s = idx >> 5, i = idx & 31;
    const float inv_f = exp2f(-(float)i * (13.287712379549449f / 32.f));
    float sn, c;
    sincosf((float)s * inv_f, &sn, &c);
    g_rope[idx] = make_float2(c, sn);
}

// ======================= mma.sync split-bf16 GEMM core ======================
// CTA 128x128, BK=32, 512 threads (16 warps, warp tile 16x64),
// 3-stage cp.async pipeline, stride-80 rows (conflict-free for ldmatrix).
#define MM_BK   32
#define MM_RS   80
#define MM_TS   (128 * MM_RS)
#define MM_STG  (4 * MM_TS)
#define MM_SMEM (3 * MM_STG)
#define MM_NIT  (EMB / MM_BK)

__device__ __forceinline__ void mm_stage_load(uint32_t stb,
                                              const __nv_bfloat16* pAh,
                                              const __nv_bfloat16* pAl,
                                              const __nv_bfloat16* pWh,
                                              const __nv_bfloat16* pWl,
                                              int k0, int tid) {
    const int row = tid >> 2, ch = tid & 3;
    const uint32_t off = (uint32_t)(row * MM_RS + ch * 16);
    const size_t goff = (size_t)row * EMB + k0 + ch * 8;
    cp_async16(stb + 0 * MM_TS + off, pAh + goff);
    cp_async16(stb + 1 * MM_TS + off, pAl + goff);
    cp_async16(stb + 2 * MM_TS + off, pWh + goff);
    cp_async16(stb + 3 * MM_TS + off, pWl + goff);
}

__device__ __forceinline__ void mm_core(const __nv_bfloat16* __restrict__ Ah,
                                        const __nv_bfloat16* __restrict__ Al,
                                        const __nv_bfloat16* __restrict__ Wh,
                                        const __nv_bfloat16* __restrict__ Wl,
                                        int m0, int n0, char* sm,
                                        float acc[8][4])
{
    const uint32_t smb = smem_to_u32(sm);
    const int tid  = threadIdx.x;
    const int lane = tid & 31;
    const int wid  = tid >> 5;
    const int wm   = wid >> 1;
    const int wn   = wid & 1;

    const __nv_bfloat16* pAh = Ah + (size_t)m0 * EMB;
    const __nv_bfloat16* pAl = Al + (size_t)m0 * EMB;
    const __nv_bfloat16* pWh = Wh + (size_t)n0 * EMB;
    const __nv_bfloat16* pWl = Wl + (size_t)n0 * EMB;

    #pragma unroll
    for (int ni = 0; ni < 8; ni++)
        #pragma unroll
        for (int j = 0; j < 4; j++) acc[ni][j] = 0.f;

    mm_stage_load(smb + 0 * MM_STG, pAh, pAl, pWh, pWl, 0, tid);
    cp_commit();
    mm_stage_load(smb + 1 * MM_STG, pAh, pAl, pWh, pWl, MM_BK, tid);
    cp_commit();

    int cs = 0, ls = 2;
    for (int k = 0; k < MM_NIT; k++) {
        cp_wait<1>();
        __syncthreads();
        const uint32_t tb = smb + cs * MM_STG;

        #pragma unroll
        for (int kk = 0; kk < 2; kk++) {
            uint32_t aH[4], aL[4];
            const uint32_t aaddr = tb + (wm * 16 + (lane & 15)) * MM_RS
                                 + kk * 32 + (lane >> 4) * 16;
            ldm_x4(aH, aaddr);
            ldm_x4(aL, aaddr + MM_TS);
            uint32_t bH[8][2], bL[8][2];
            #pragma unroll
            for (int p = 0; p < 4; p++) {
                const uint32_t row = wn * 64 + p * 16 + (lane & 7) + ((lane >> 4) << 3);
                const uint32_t baddr = tb + 2 * MM_TS + row * MM_RS
                                     + kk * 32 + ((lane >> 3) & 1) * 16;
                ldm_x4(&bH[2 * p][0], baddr);
                ldm_x4(&bL[2 * p][0], baddr + MM_TS);
            }
            #pragma unroll
            for (int ni = 0; ni < 8; ni++) {
                mma_bf16(acc[ni], aH, bH[ni]);
                mma_bf16(acc[ni], aH, bL[ni]);
                mma_bf16(acc[ni], aL, bH[ni]);
            }
        }

        if (k + 2 < MM_NIT)
            mm_stage_load(smb + ls * MM_STG, pAh, pAl, pWh, pWl, (k + 2) * MM_BK, tid);
        cp_commit();
        cs = (cs == 2) ? 0 : cs + 1;
        ls = (ls == 2) ? 0 : ls + 1;
    }
}

// ---- QKV projection: fused bias+scale+RoPE, outputs fp16 attention operands
__global__ __launch_bounds__(512, 1) void mm_qkv(const float* __restrict__ bq,
                                                 const float* __restrict__ bk,
                                                 const float* __restrict__ bv) {
    extern __shared__ __align__(16) char mmsm[];
    const int z = blockIdx.z;
    const __nv_bfloat16* Wh = g_wh + (size_t)z * EMB * EMB;
    const __nv_bfloat16* Wl = g_wl + (size_t)z * EMB * EMB;
    const float* bias = (z == 0) ? bq : (z == 1) ? bk : bv;
    const float scale = (z == 0) ? 0.125f : 1.0f;   // hd^-0.5
    const bool rope = (z < 2);

    const int m0 = blockIdx.y * 128, n0 = blockIdx.x * 128;
    float acc[8][4];
    mm_core(g_xh, g_xl, Wh, Wl, m0, n0, mmsm, acc);

    const int lane = threadIdx.x & 31;
    const int wid  = threadIdx.x >> 5;
    const int wm = wid >> 1, wn = wid & 1;
    const int hh = (n0 + wn * 64) >> 6;
    const int dbase = (lane & 3) * 2;

    #pragma unroll
    for (int half = 0; half < 2; half++) {
        const int row = m0 + wm * 16 + (lane >> 2) + half * 8;
        const int s = row >> 1, bb = row & 1;
        float xv[8][2];
        #pragma unroll
        for (int ni = 0; ni < 8; ni++) {
            const int c = n0 + wn * 64 + ni * 8 + dbase;
            xv[ni][0] = (acc[ni][half * 2 + 0] + bias[c])     * scale;
            xv[ni][1] = (acc[ni][half * 2 + 1] + bias[c + 1]) * scale;
        }
        if (rope) {
            #pragma unroll
            for (int t = 0; t < 4; t++) {
                const int i0 = t * 8 + dbase;
                const float2 cs0 = g_rope[s * 32 + i0];
                const float2 cs1 = g_rope[s * 32 + i0 + 1];
                const float lo0 = xv[t][0],     lo1 = xv[t][1];
                const float hi0 = xv[t + 4][0], hi1 = xv[t + 4][1];
                xv[t][0]     = lo0 * cs0.x - hi0 * cs0.y;
                xv[t][1]     = lo1 * cs1.x - hi1 * cs1.y;
                xv[t + 4][0] = hi0 * cs0.x + lo0 * cs0.y;
                xv[t + 4][1] = hi1 * cs1.x + lo1 * cs1.y;
            }
        }
        const size_t base = ((size_t)(bb * NH + hh) * SEQ + s) * HD;
        if (z == 0) {
            #pragma unroll
            for (int ni = 0; ni < 8; ni++) {
                const size_t off = base + ni * 8 + dbase;
                __half2 h = __floats2half2_rn(xv[ni][0], xv[ni][1]);
                float2 hf = __half22float2(h);
                __half2 l = __floats2half2_rn(xv[ni][0] - hf.x, xv[ni][1] - hf.y);
                *(__half2*)(g_qhh + off) = h;
                *(__half2*)(g_qhl + off) = l;
            }
        } else {
            __half* dst = (z == 1) ? g_kf : g_vf;
            #pragma unroll
            for (int ni = 0; ni < 8; ni++) {
                const size_t off = base + ni * 8 + dbase;
                *(__half2*)(dst + off) = __floats2half2_rn(xv[ni][0], xv[ni][1]);
            }
        }
    }
}

// ---- output projection: plain fp32 epilogue -------------------------------
__global__ __launch_bounds__(512, 1) void mm_out(const float* __restrict__ bo,
                                                 float* __restrict__ out) {
    extern __shared__ __align__(16) char mmsm[];
    const int m0 = blockIdx.y * 128, n0 = blockIdx.x * 128;
    float acc[8][4];
    mm_core(g_ah, g_al, g_wh + (size_t)3 * EMB * EMB,
            g_wl + (size_t)3 * EMB * EMB, m0, n0, mmsm, acc);

    const int lane = threadIdx.x & 31;
    const int wid  = threadIdx.x >> 5;
    const int wm = wid >> 1, wn = wid & 1;
    #pragma unroll
    for (int ni = 0; ni < 8; ni++) {
        const int r = m0 + wm * 16 + (lane >> 2);
        const int c = n0 + wn * 64 + ni * 8 + (lane & 3) * 2;
        float2 v0, v1;
        v0.x = acc[ni][0] + bo[c];
        v0.y = acc[ni][1] + bo[c + 1];
        v1.x = acc[ni][2] + bo[c];
        v1.y = acc[ni][3] + bo[c + 1];
        *(float2*)(out + (size_t)r * EMB + c)       = v0;
        *(float2*)(out + (size_t)(r + 8) * EMB + c) = v1;
    }
}

// ================= tensor-core flash attention (fp16, Q split) =============
// Q = Qh + Ql (fp16 pair, error 2^-24); K, V, P single fp16.
// S: 2 MMAs / tile-pair, PV: 1 MMA. KV tiles of 64 in 3-stage cp.async ring.
#define ABKV   64
#define A_RS   144
#define A_KT   (64 * A_RS)               // 9216 per tile
#define A_STG  (2 * A_KT)                // K + V = 18432
#define A_SMEM (3 * A_STG)               // 55296
#define A_NT   (SEQ / ABKV)              // 32

__device__ __forceinline__ void kv_load(uint32_t stb, int g, int kv0, int tid) {
    #pragma unroll
    for (int i = 0; i < 4; i++) {
        const int gid  = i * 256 + tid;
        const int tile = gid >> 9;                  // 0 = K, 1 = V
        const int gi   = gid & 511;
        const int row  = gi >> 3, ch = gi & 7;
        const __half* base = tile ? g_vf : g_kf;
        const void* src = base + ((size_t)g * SEQ + kv0 + row) * HD + ch * 8;
        cp_async16(stb + tile * A_KT + row * A_RS + ch * 16, src);
    }
}

__global__ __launch_bounds__(256, 1) void attn_mma() {
    extern __shared__ __align__(16) char dynsm[];
    const uint32_t smb = smem_to_u32(dynsm);
    const int g  = blockIdx.y;
    const int qb = blockIdx.x;
    const int tid = threadIdx.x, lane = tid & 31, wid = tid >> 5;

    // ---- stage Q (hi then lo) through smem -> register fragments ----
    uint32_t qhf[4][4], qlf[4][4];
    {
        const __half* qsrc[2] = { g_qhh, g_qhl };
        for (int pass = 0; pass < 2; pass++) {
            #pragma unroll
            for (int i = 0; i < 4; i++) {
                const int gid = i * 256 + tid;
                const int row = gid >> 3, ch = gid & 7;
                *(uint4*)(dynsm + row * A_RS + ch * 16) =
                    *(const uint4*)(qsrc[pass] + ((size_t)g * SEQ + qb * 128 + row) * HD + ch * 8);
            }
            __syncthreads();
            #pragma unroll
            for (int kt = 0; kt < 4; kt++) {
                const uint32_t addr = smb + (wid * 16 + (lane & 15)) * A_RS
                                    + kt * 32 + (lane >> 4) * 16;
                ldm_x4(pass ? qlf[kt] : qhf[kt], addr);
            }
            __syncthreads();
        }
    }

    float O[8][4];
    #pragma unroll
    for (int nd = 0; nd < 8; nd++)
        #pragma unroll
        for (int j = 0; j < 4; j++) O[nd][j] = 0.f;
    float m_lo = -1e30f, m_hi = -1e30f, l_lo = 0.f, l_hi = 0.f;

    // prologue: stages 0, 1
    kv_load(smb + 0 * A_STG, g, 0, tid);
    cp_commit();
    kv_load(smb + 1 * A_STG, g, ABKV, tid);
    cp_commit();

    int cs = 0, ls = 2;
    for (int t = 0; t < A_NT; t++) {
        cp_wait<1>();
        __syncthreads();
        const uint32_t stb = smb + cs * A_STG;

        // ---- S = (Qh + Ql) K^T : 2 MMAs per n-tile ----
        float S[8][4];
        #pragma unroll
        for (int nt = 0; nt < 8; nt++)
            #pragma unroll
            for (int j = 0; j < 4; j++) S[nt][j] = 0.f;
        #pragma unroll
        for (int kt = 0; kt < 4; kt++) {
            #pragma unroll
            for (int p = 0; p < 4; p++) {
                uint32_t bh[4];
                const uint32_t row = p * 16 + (lane & 7) + ((lane >> 4) << 3);
                const uint32_t addr = stb + row * A_RS + kt * 32 + ((lane >> 3) & 1) * 16;
                ldm_x4(bh, addr);
                mma_f16(S[2 * p],     qhf[kt], &bh[0]);
                mma_f16(S[2 * p],     qlf[kt], &bh[0]);
                mma_f16(S[2 * p + 1], qhf[kt], &bh[2]);
                mma_f16(S[2 * p + 1], qlf[kt], &bh[2]);
            }
        }

        // ---- online softmax ----
        float tm_lo = -1e30f, tm_hi = -1e30f;
        #pragma unroll
        for (int nt = 0; nt < 8; nt++) {
            tm_lo = fmaxf(tm_lo, fmaxf(S[nt][0], S[nt][1]));
            tm_hi = fmaxf(tm_hi, fmaxf(S[nt][2], S[nt][3]));
        }
        tm_lo = fmaxf(tm_lo, __shfl_xor_sync(0xffffffffu, tm_lo, 1));
        tm_lo = fmaxf(tm_lo, __shfl_xor_sync(0xffffffffu, tm_lo, 2));
        tm_hi = fmaxf(tm_hi, __shfl_xor_sync(0xffffffffu, tm_hi, 1));
        tm_hi = fmaxf(tm_hi, __shfl_xor_sync(0xffffffffu, tm_hi, 2));

        const float mn_lo = fmaxf(m_lo, tm_lo);
        const float mn_hi = fmaxf(m_hi, tm_hi);
        const float corr_lo = ex2((m_lo - mn_lo) * L2E);
        const float corr_hi = ex2((m_hi - mn_hi) * L2E);
        m_lo = mn_lo; m_hi = mn_hi;
        l_lo *= corr_lo; l_hi *= corr_hi;
        #pragma unroll
        for (int nd = 0; nd < 8; nd++) {
            O[nd][0] *= corr_lo; O[nd][1] *= corr_lo;
            O[nd][2] *= corr_hi; O[nd][3] *= corr_hi;
        }
        const float mb_lo = mn_lo * L2E, mb_hi = mn_hi * L2E;

        // ---- P = exp(S - m), single fp16 ----
        uint32_t aP[4][4];
        #pragma unroll
        for (int kt = 0; kt < 4; kt++) {
            #pragma unroll
            for (int half = 0; half < 2; half++) {
                const int nt = 2 * kt + half;
                const float p0 = ex2(fmaf(S[nt][0], L2E, -mb_lo));
                const float p1 = ex2(fmaf(S[nt][1], L2E, -mb_lo));
                const float p2 = ex2(fmaf(S[nt][2], L2E, -mb_hi));
                const float p3 = ex2(fmaf(S[nt][3], L2E, -mb_hi));
                l_lo += p0 + p1; l_hi += p2 + p3;
                aP[kt][half * 2 + 0] = h2u(__floats2half2_rn(p0, p1));
                aP[kt][half * 2 + 1] = h2u(__floats2half2_rn(p2, p3));
            }
        }

        // ---- O += P V : 1 MMA per (kt, d-tile-pair) ----
        #pragma unroll
        for (int kt = 0; kt < 4; kt++) {
            #pragma unroll
            for (int ndp = 0; ndp < 4; ndp++) {
                uint32_t vh[4];
                const uint32_t addr = stb + A_KT
                                    + (kt * 16 + (lane & 15)) * A_RS
                                    + ndp * 32 + (lane >> 4) * 16;
                ldm_x4_t(vh, addr);
                mma_f16(O[2 * ndp],     aP[kt], &vh[0]);
                mma_f16(O[2 * ndp + 1], aP[kt], &vh[2]);
            }
        }

        if (t + 2 < A_NT)
            kv_load(smb + ls * A_STG, g, (t + 2) * ABKV, tid);
        cp_commit();
        cs = (cs == 2) ? 0 : cs + 1;
        ls = (ls == 2) ? 0 : ls + 1;
    }

    // ---- finalize: normalize, split bf16 hi/lo, token-row layout ----
    l_lo += __shfl_xor_sync(0xffffffffu, l_lo, 1);
    l_lo += __shfl_xor_sync(0xffffffffu, l_lo, 2);
    l_hi += __shfl_xor_sync(0xffffffffu, l_hi, 1);
    l_hi += __shfl_xor_sync(0xffffffffu, l_hi, 2);
    const float il_lo = 1.f / l_lo, il_hi = 1.f / l_hi;

    const int b  = g >> 4;
    const int hh = g & 15;
    const int r0 = qb * 128 + wid * 16 + (lane >> 2);
    #pragma unroll
    for (int nd = 0; nd < 8; nd++) {
        const int col = hh * HD + nd * 8 + (lane & 3) * 2;
        {
            const float v0 = O[nd][0] * il_lo, v1 = O[nd][1] * il_lo;
            __nv_bfloat162 h = __floats2bfloat162_rn(v0, v1);
            __nv_bfloat162 l = __floats2bfloat162_rn(v0 - __bfloat162float(h.x),
                                                     v1 - __bfloat162float(h.y));
            const size_t off = (size_t)(r0 * BATCH + b) * EMB + col;
            *(__nv_bfloat162*)(g_ah + off) = h;
            *(__nv_bfloat162*)(g_al + off) = l;
        }
        {
            const float v0 = O[nd][2] * il_hi, v1 = O[nd][3] * il_hi;
            __nv_bfloat162 h = __floats2bfloat162_rn(v0, v1);
            __nv_bfloat162 l = __floats2bfloat162_rn(v0 - __bfloat162float(h.x),
                                                     v1 - __bfloat162float(h.y));
            const size_t off = (size_t)((r0 + 8) * BATCH + b) * EMB + col;
            *(__nv_bfloat162*)(g_ah + off) = h;
            *(__nv_bfloat162*)(g_al + off) = l;
        }
    }
}

// ---------------- launch ----------------------------------------------------
extern "C" void kernel_launch(void* const* d_in, const int* in_sizes, int n_in,
                              void* d_out, int out_size) {
    (void)in_sizes; (void)n_in; (void)out_size;
    const float* query = (const float*)d_in[0];
    const float* bq    = (const float*)d_in[2];
    const float* bk    = (const float*)d_in[4];
    const float* bv    = (const float*)d_in[6];
    const float* bo    = (const float*)d_in[8];
    float* out = (float*)d_out;

    cudaFuncSetAttribute(mm_qkv,   cudaFuncAttributeMaxDynamicSharedMemorySize, MM_SMEM);
    cudaFuncSetAttribute(mm_out,   cudaFuncAttributeMaxDynamicSharedMemorySize, MM_SMEM);
    cudaFuncSetAttribute(attn_mma, cudaFuncAttributeMaxDynamicSharedMemorySize, A_SMEM);

    __nv_bfloat16* xh; __nv_bfloat16* xl;
    cudaGetSymbolAddress((void**)&xh, g_xh);
    cudaGetSymbolAddress((void**)&xl, g_xl);

    // 0) fp32 -> bf16 hi/lo splits (X and weights) + rope table
    cvt_split<<<MROWS * EMB / 1024, 256>>>(query, xh, xl);
    dim3 gw(EMB * EMB / 1024, 1, 4);
    cvt_w<<<gw, 256>>>((const float*)d_in[1], (const float*)d_in[3],
                       (const float*)d_in[5], (const float*)d_in[7]);
    rope_table<<<SEQ * 32 / 256, 256>>>();

    // 1) fused QKV projection + bias + scale + RoPE -> fp16 attention operands
    dim3 gq(EMB / 128, MROWS / 128, 3);
    mm_qkv<<<gq, 512, MM_SMEM>>>(bq, bk, bv);

    // 2) fp16 tensor-core flash attention (writes g_ah/g_al split bf16)
    dim3 ga(SEQ / 128, NHEADS);
    attn_mma<<<ga, 256, A_SMEM>>>();

    // 3) output projection (3xBF16)
    dim3 go(EMB / 128, MROWS / 128);
    mm_out<<<go, 512, MM_SMEM>>>(bo, out);
}